// round 12
// baseline (speedup 1.0000x reference)
#include <cuda_runtime.h>
#include <cuda_fp16.h>
#include <cstdint>

#define NB 2
#define NC 128
#define NN 4096      // H*W
#define NHD 8        // heads
#define DH 16        // head dim
#define NG 8         // groupnorm groups
#define GN_EPS 1e-5f
#define CSCALE 0.36067376022224085f   // 0.25 * log2(e)

// ======================= PTX helpers (baseline sm_80+ features only) =======
__device__ __forceinline__ uint32_t smem_u32(const void* p) {
    uint32_t a;
    asm("{ .reg .u64 t; cvta.to.shared.u64 t, %1; cvt.u32.u64 %0, t; }" : "=r"(a) : "l"(p));
    return a;
}
__device__ __forceinline__ void ldsm_x4(uint32_t* r, uint32_t a) {
    asm volatile("ldmatrix.sync.aligned.m8n8.x4.shared.b16 {%0,%1,%2,%3}, [%4];"
        : "=r"(r[0]), "=r"(r[1]), "=r"(r[2]), "=r"(r[3]) : "r"(a));
}
__device__ __forceinline__ void ldsm_x4t(uint32_t* r, uint32_t a) {
    asm volatile("ldmatrix.sync.aligned.m8n8.x4.trans.shared.b16 {%0,%1,%2,%3}, [%4];"
        : "=r"(r[0]), "=r"(r[1]), "=r"(r[2]), "=r"(r[3]) : "r"(a));
}
__device__ __forceinline__ void mma_fp16(float* d, const uint32_t* a,
                                         const uint32_t* b, const float* c) {
    asm volatile("mma.sync.aligned.m16n8k16.row.col.f32.f16.f16.f32 "
        "{%0,%1,%2,%3},{%4,%5,%6,%7},{%8,%9},{%10,%11,%12,%13};"
        : "=f"(d[0]), "=f"(d[1]), "=f"(d[2]), "=f"(d[3])
        : "r"(a[0]), "r"(a[1]), "r"(a[2]), "r"(a[3]), "r"(b[0]), "r"(b[1]),
          "f"(c[0]), "f"(c[1]), "f"(c[2]), "f"(c[3]));
}
// f16-accumulator HMMA: D packed f16x2 {rows r | rows r+8}
__device__ __forceinline__ void mma_h16(uint32_t* d, const uint32_t* a, const uint32_t* b) {
    uint32_t z = 0u;
    asm volatile("mma.sync.aligned.m16n8k16.row.col.f16.f16.f16.f16 "
        "{%0,%1},{%2,%3,%4,%5},{%6,%7},{%8,%9};"
        : "=r"(d[0]), "=r"(d[1])
        : "r"(a[0]), "r"(a[1]), "r"(a[2]), "r"(a[3]), "r"(b[0]), "r"(b[1]),
          "r"(z), "r"(z));
}
__device__ __forceinline__ uint32_t ex2h2(uint32_t h) {
    asm("ex2.approx.f16x2 %0, %1;" : "=r"(h) : "r"(h)); return h;
}
__device__ __forceinline__ uint32_t hadd2u(uint32_t a, uint32_t b) {
    uint32_t d; asm("add.rn.f16x2 %0, %1, %2;" : "=r"(d) : "r"(a), "r"(b)); return d;
}
__device__ __forceinline__ uint32_t f2h2(float lo, float hi) {
    __half2 h = __floats2half2_rn(lo, hi);
    return *reinterpret_cast<uint32_t*>(&h);
}

// ======================= scratch =============================================
__device__ __half g_q  [NB*NHD*NN*DH];   // [b,h,n,d], pre-scaled by CSCALE
__device__ __half g_k  [NB*NHD*NN*DH];   // [b,h,n,d]
__device__ __half g_v  [NB*NHD*NN*DH];   // [b,h,n,d]
__device__ __half g_aoh[NB*NN*NC];       // attention out fp16, [b,n,c]
__device__ float  g_proj[NB*NC*NN];      // out-proj fp32, channel-major [b,c,n]
__device__ float2 g_part[NB*NG*64];      // GN partial (sum, sumsq) per token-chunk
__device__ __align__(16) __half g_wh[4*NC*NC];  // fp16 weights: Wq,Wk,Wv,Wo

// ======================= Kernel W: weight fp32 -> fp16 once =================
__global__ __launch_bounds__(256) void wcvt_kernel(
    const float* __restrict__ Wq, const float* __restrict__ Wk,
    const float* __restrict__ Wv, const float* __restrict__ Wo)
{
    int i = blockIdx.x * 256 + threadIdx.x;     // float2 units, 0..32767
    int m = i >> 13, o = i & 8191;
    const float* src = (m == 0) ? Wq : (m == 1) ? Wk : (m == 2) ? Wv : Wo;
    float2 v = ((const float2*)src)[o];
    *(uint32_t*)(g_wh + (size_t)m*16384 + o*2) = f2h2(v.x, v.y);
}

// ======================= Kernel A: QKV projection (256 threads) =============
// grid (NB*64, 3): 64 tokens x 128 outcols per CTA; 8 warps = 4 m-tiles x 2 halves.
__global__ __launch_bounds__(256) void qkv_mma_kernel(
    const float* __restrict__ x,
    const float* __restrict__ bq, const float* __restrict__ bk,
    const float* __restrict__ bv)
{
    __shared__ __align__(16) __half xs[64*136];
    __shared__ __align__(16) __half ws[128*72];
    __shared__ float bs[128];

    const int bi = blockIdx.x >> 6;
    const int n0 = (blockIdx.x & 63) * 64;
    const int m  = blockIdx.y;
    const int tid = threadIdx.x, lane = tid & 31, wid = tid >> 5;
    const int mt = wid & 3, gh = wid >> 2;

    const __half* __restrict__ wsrc = g_wh + (size_t)m*16384;
    const float* __restrict__ bias  = (m == 0) ? bq : (m == 1) ? bk : bv;
    __half* __restrict__ outp       = (m == 0) ? g_q : (m == 1) ? g_k : g_v;
    const float s = (m == 0) ? CSCALE : 1.f;

    if (tid < 128) bs[tid] = bias[tid];

    {   // x tile [c=128][n=64] -> xs[n][c] fp16 (256 threads: 32 cols each)
        const int row = tid & 63, ch = (tid >> 6) * 32;
        const float* xp = x + (size_t)(bi*NC + ch)*NN + n0 + row;
        #pragma unroll 4
        for (int cc = 0; cc < 32; cc += 2) {
            float a = xp[(size_t)cc*NN];
            float b = xp[(size_t)(cc+1)*NN];
            *(uint32_t*)(xs + row*136 + ch + cc) = f2h2(a, b);
        }
    }
    __syncthreads();

    uint32_t qa[8][4];   // warp's 16 token rows, all 8 k-steps
    {
        uint32_t base = smem_u32(xs) +
            ((uint32_t)(mt*16 + (lane & 15))*136 + ((lane >> 4) & 1)*8)*2;
        #pragma unroll
        for (int k = 0; k < 8; ++k) ldsm_x4(qa[k], base + (uint32_t)k*32);
    }

    float of[8][4];
    #pragma unroll
    for (int t = 0; t < 8; ++t)
        #pragma unroll
        for (int j = 0; j < 4; ++j) of[t][j] = 0.f;

    for (int ph = 0; ph < 2; ++ph) {
        __syncthreads();
        #pragma unroll
        for (int i = tid; i < 1024; i += 256) {    // fp16 weight copy
            int d = i >> 3, u = i & 7;
            *(uint4*)(ws + d*72 + u*8) = *(const uint4*)(wsrc + d*128 + ph*64 + u*8);
        }
        __syncthreads();
        #pragma unroll
        for (int kk = 0; kk < 4; ++kk) {
            const int k = ph*4 + kk;
            uint32_t bbase = smem_u32(ws) +
                ((uint32_t)(gh*64 + ((lane >> 4) & 1)*8 + (lane & 7))*72)*2 +
                (uint32_t)kk*32 + ((lane >> 3) & 1)*16;
            #pragma unroll
            for (int g = 0; g < 4; ++g) {
                uint32_t bb[4];
                ldsm_x4(bb, bbase + (uint32_t)g*16*72*2);
                mma_fp16(of[2*g],   qa[k], bb,     of[2*g]);
                mma_fp16(of[2*g+1], qa[k], bb + 2, of[2*g+1]);
            }
        }
    }

    const int r = mt*16 + (lane >> 2);
    #pragma unroll
    for (int nt = 0; nt < 8; ++nt) {
        int c0 = gh*64 + (nt >> 1)*16 + (nt & 1)*8 + (lane & 3)*2;
        int h = c0 >> 4, d = c0 & 15;
        __half* dst = outp + ((size_t)((bi*NHD + h)*NN) + n0 + r)*DH + d;
        *(uint32_t*)dst          = f2h2((of[nt][0]+bs[c0])*s, (of[nt][1]+bs[c0+1])*s);
        *(uint32_t*)(dst + 8*DH) = f2h2((of[nt][2]+bs[c0])*s, (of[nt][3]+bs[c0+1])*s);
    }
}

// ======================= Kernel B: HMMA flash attention (f16-acc, x4t V) ====
__global__ __launch_bounds__(128) void attn_mma_kernel()
{
    __shared__ __align__(16) __half qs[128*24];
    __shared__ __align__(16) __half ks[128*24];
    __shared__ __align__(16) __half vs[128*24];

    const int bh = blockIdx.x;
    const int n0 = blockIdx.y * 128;
    const int tid = threadIdx.x, lane = tid & 31, wid = tid >> 5;

    const __half* __restrict__ qg = g_q + (size_t)bh*NN*DH;
    const __half* __restrict__ kg = g_k + (size_t)bh*NN*DH;
    const __half* __restrict__ vg = g_v + (size_t)bh*NN*DH;

    {
        const uint4* q4 = (const uint4*)(qg + (size_t)(n0 + tid)*DH);
        *(uint4*)(qs + tid*24)     = q4[0];
        *(uint4*)(qs + tid*24 + 8) = q4[1];
    }
    uint4 pk0, pk1, pv0, pv1;
    {
        const uint4* kp = (const uint4*)(kg + (size_t)tid*DH);
        pk0 = kp[0]; pk1 = kp[1];
        const uint4* vp = (const uint4*)(vg + (size_t)tid*DH);
        pv0 = vp[0]; pv1 = vp[1];
    }
    __syncthreads();

    uint32_t qa[2][4];
    #pragma unroll
    for (int mt = 0; mt < 2; ++mt)
        ldsm_x4(qa[mt], smem_u32(qs) +
            ((uint32_t)(wid*32 + mt*16 + (lane & 15))*24 + ((lane >> 4) & 1)*8)*2);

    float of[2][2][4];
    #pragma unroll
    for (int a = 0; a < 2; ++a)
        #pragma unroll
        for (int b = 0; b < 2; ++b)
            #pragma unroll
            for (int c = 0; c < 4; ++c) of[a][b][c] = 0.f;
    float lf[4] = {0.f, 0.f, 0.f, 0.f};

    const uint32_t kaddr = smem_u32(ks) +
        (uint32_t)(((lane >> 4) & 1)*8 + (lane & 7))*48 + ((lane >> 3) & 1)*16;
    const uint32_t vaddr4 = smem_u32(vs) +
        (uint32_t)(lane & 15)*48 + ((lane >> 4) & 1)*16;

    for (int it = 0; it < 32; ++it) {
        __syncthreads();
        *(uint4*)(ks + tid*24)     = pk0;
        *(uint4*)(ks + tid*24 + 8) = pk1;
        *(uint4*)(vs + tid*24)     = pv0;
        *(uint4*)(vs + tid*24 + 8) = pv1;
        if (it + 1 < 32) {
            const int kt = (it + 1) * 128;
            const uint4* kp = (const uint4*)(kg + (size_t)(kt + tid)*DH);
            pk0 = kp[0]; pk1 = kp[1];
            const uint4* vp = (const uint4*)(vg + (size_t)(kt + tid)*DH);
            pv0 = vp[0]; pv1 = vp[1];
        }
        __syncthreads();

        uint32_t lh[4] = {0u, 0u, 0u, 0u};
        uint32_t kb[4];
        uint32_t scb[2][8];                 // ping-pong f16x2 scores
        ldsm_x4(kb, kaddr);
        mma_h16(scb[0]+0, qa[0], kb);
        mma_h16(scb[0]+2, qa[0], kb + 2);
        mma_h16(scb[0]+4, qa[1], kb);
        mma_h16(scb[0]+6, qa[1], kb + 2);

        #pragma unroll
        for (int k4 = 0; k4 < 8; ++k4) {
            const int cur = k4 & 1, nxt = cur ^ 1;
            if (k4 < 7) {                  // QK(k4+1) overlaps exp/PV(k4)
                ldsm_x4(kb, kaddr + (uint32_t)(k4+1)*768);
                mma_h16(scb[nxt]+0, qa[0], kb);
                mma_h16(scb[nxt]+2, qa[0], kb + 2);
                mma_h16(scb[nxt]+4, qa[1], kb);
                mma_h16(scb[nxt]+6, qa[1], kb + 2);
            }
            uint32_t vb[4];                // one x4t: {k0-7,k8-15} x {n0-7,n8-15}
            ldsm_x4t(vb, vaddr4 + (uint32_t)k4*768);
            #pragma unroll
            for (int mt = 0; mt < 2; ++mt) {
                uint32_t pa[4];
                pa[0] = ex2h2(scb[cur][mt*4+0]);
                pa[1] = ex2h2(scb[cur][mt*4+1]);
                pa[2] = ex2h2(scb[cur][mt*4+2]);
                pa[3] = ex2h2(scb[cur][mt*4+3]);
                lh[mt*2]   = hadd2u(lh[mt*2],   hadd2u(pa[0], pa[2]));
                lh[mt*2+1] = hadd2u(lh[mt*2+1], hadd2u(pa[1], pa[3]));
                mma_fp16(of[mt][0], pa, vb,     of[mt][0]);
                mma_fp16(of[mt][1], pa, vb + 2, of[mt][1]);
            }
        }
        #pragma unroll
        for (int i = 0; i < 4; ++i) {
            float2 f = __half22float2(*reinterpret_cast<__half2*>(&lh[i]));
            lf[i] += f.x + f.y;
        }
    }

    const int b = bh >> 3, h = bh & 7;
    #pragma unroll
    for (int mt = 0; mt < 2; ++mt) {
        #pragma unroll
        for (int rr = 0; rr < 2; ++rr) {
            float l = lf[mt*2 + rr];
            l += __shfl_xor_sync(0xffffffffu, l, 1);
            l += __shfl_xor_sync(0xffffffffu, l, 2);
            float inv = 1.f / l;
            int r = wid*32 + mt*16 + rr*8 + (lane >> 2);
            __half* dst = g_aoh + ((size_t)(b*NN) + n0 + r)*NC + h*16 + (lane & 3)*2;
            *(uint32_t*)dst       = f2h2(of[mt][0][rr*2]*inv, of[mt][0][rr*2+1]*inv);
            *(uint32_t*)(dst + 8) = f2h2(of[mt][1][rr*2]*inv, of[mt][1][rr*2+1]*inv);
        }
    }
}

// ======================= Kernel C: output projection (256 threads) ==========
// grid NB*128: CTA = (bi, 64-token chunk, 64-outcol half); 8 warps = 4 m x 2 q.
__global__ __launch_bounds__(256) void oproj_mma_kernel(const float* __restrict__ bo)
{
    __shared__ __align__(16) __half as_[64*136];
    __shared__ __align__(16) __half ws[64*136];
    __shared__ float bs[64];
    __shared__ float ws1[8][2], ws2[8][2];

    const int bi = blockIdx.x >> 7;
    const int rest = blockIdx.x & 127;
    const int chunk = rest >> 1;
    const int half = rest & 1;
    const int n0 = chunk * 64;
    const int tid = threadIdx.x, lane = tid & 31, wid = tid >> 5;
    const int mt = wid & 3, gh = wid >> 2;       // m-tile, 32-col quarter
    const __half* __restrict__ wsrc = g_wh + (size_t)3*16384 + (size_t)half*64*128;

    if (tid < 64) bs[tid] = bo[half*64 + tid];

    for (int idx = tid; idx < 64*64; idx += 256) {   // aoh tile (full K=128)
        int row = idx >> 6, u = idx & 63;
        uint32_t v = ((const uint32_t*)(g_aoh + ((size_t)(bi*NN) + n0 + row)*NC))[u];
        *(uint32_t*)(as_ + row*136 + u*2) = v;
    }
    #pragma unroll
    for (int i = tid; i < 1024; i += 256) {          // 64 weight rows x 128 k
        int d = i >> 4, u = i & 15;
        *(uint4*)(ws + d*136 + u*8) = ((const uint4*)wsrc)[d*16 + u];
    }
    __syncthreads();

    uint32_t qa[8][4];   // warp's 16 token rows
    {
        uint32_t base = smem_u32(as_) +
            ((uint32_t)(mt*16 + (lane & 15))*136 + ((lane >> 4) & 1)*8)*2;
        #pragma unroll
        for (int k = 0; k < 8; ++k) ldsm_x4(qa[k], base + (uint32_t)k*32);
    }

    float of[4][4];
    #pragma unroll
    for (int t = 0; t < 4; ++t)
        #pragma unroll
        for (int j = 0; j < 4; ++j) of[t][j] = 0.f;

    #pragma unroll
    for (int k = 0; k < 8; ++k) {
        uint32_t bbase = smem_u32(ws) +
            ((uint32_t)(gh*32 + ((lane >> 4) & 1)*8 + (lane & 7))*136)*2 +
            (uint32_t)k*32 + ((lane >> 3) & 1)*16;
        #pragma unroll
        for (int g = 0; g < 2; ++g) {
            uint32_t bb[4];
            ldsm_x4(bb, bbase + (uint32_t)g*16*136*2);
            mma_fp16(of[2*g],   qa[k], bb,     of[2*g]);
            mma_fp16(of[2*g+1], qa[k], bb + 2, of[2*g+1]);
        }
    }

    // epilogue: bias, store g_proj, per-group (sum,sumsq) for 2 local groups
    const int r = mt*16 + (lane >> 2);
    float gs1[2] = {0.f, 0.f}, gs2[2] = {0.f, 0.f};

    #pragma unroll
    for (int nt = 0; nt < 4; ++nt) {
        int c0l = gh*32 + (nt >> 1)*16 + (nt & 1)*8 + (lane & 3)*2;
        int c0 = half*64 + c0l;
        float v0 = of[nt][0] + bs[c0l];
        float v1 = of[nt][1] + bs[c0l+1];
        float v2 = of[nt][2] + bs[c0l];
        float v3 = of[nt][3] + bs[c0l+1];
        float* d0 = g_proj + (size_t)(bi*NC + c0)*NN + n0 + r;
        float* d1 = g_proj + (size_t)(bi*NC + c0 + 1)*NN + n0 + r;
        d0[0] = v0; d1[0] = v1; d0[8] = v2; d1[8] = v3;
        int gl = nt >> 1;
        gs1[gl] += (v0 + v1) + (v2 + v3);
        gs2[gl] += (v0*v0 + v1*v1) + (v2*v2 + v3*v3);
    }
    #pragma unroll
    for (int g = 0; g < 2; ++g) {
        float s1 = gs1[g], s2 = gs2[g];
        #pragma unroll
        for (int o = 16; o > 0; o >>= 1) {
            s1 += __shfl_xor_sync(0xffffffffu, s1, o);
            s2 += __shfl_xor_sync(0xffffffffu, s2, o);
        }
        if (lane == 0) { ws1[wid][g] = s1; ws2[wid][g] = s2; }
    }
    __syncthreads();
    if (tid < 4) {   // local group tid = gh_*2 + gl; warps gh_*4 + mt, mt 0..3
        int gh_ = tid >> 1, gl = tid & 1;
        float S1 = ws1[gh_*4+0][gl] + ws1[gh_*4+1][gl] + ws1[gh_*4+2][gl] + ws1[gh_*4+3][gl];
        float S2 = ws2[gh_*4+0][gl] + ws2[gh_*4+1][gl] + ws2[gh_*4+2][gl] + ws2[gh_*4+3][gl];
        g_part[(bi*NG + half*4 + tid)*64 + chunk] = make_float2(S1, S2);
    }
}

// ======================= Kernel E: GN apply + residual (MLP 4) ==============
__global__ __launch_bounds__(256) void gnapply_kernel(
    const float* __restrict__ x,
    const float* __restrict__ gn_w, const float* __restrict__ gn_b,
    float* __restrict__ out)
{
    __shared__ float2 st_s;
    const int tid = threadIdx.x;
    if (tid < 32) {
        int bg = blockIdx.x >> 5;            // 32 blocks per (b,g)
        float S1 = 0.f, S2 = 0.f;
        #pragma unroll
        for (int c = tid; c < 64; c += 32) {
            float2 pp = g_part[bg*64 + c];
            S1 += pp.x; S2 += pp.y;
        }
        #pragma unroll
        for (int o = 16; o > 0; o >>= 1) {
            S1 += __shfl_xor_sync(0xffffffffu, S1, o);
            S2 += __shfl_xor_sync(0xffffffffu, S2, o);
        }
        if (tid == 0) {
            const float invn = 1.f / (16.f * NN);
            float mean = S1 * invn;
            float var  = S2 * invn - mean*mean;
            st_s = make_float2(mean, rsqrtf(var + GN_EPS));
        }
    }

    int ia = blockIdx.x * 512 + tid;
    int ib = ia + 256;
    float4 pva = ((const float4*)g_proj)[ia];
    float4 xva = ((const float4*)x)[ia];
    float4 pvb = ((const float4*)g_proj)[ib];
    float4 xvb = ((const float4*)x)[ib];
    int ca = (ia >> 10) & 127, cb = (ib >> 10) & 127;
    float gwa = gn_w[ca], gba = gn_b[ca];
    float gwb = gn_w[cb], gbb = gn_b[cb];

    __syncthreads();
    float2 st = st_s;
    float wa = gwa * st.y, wb = gwb * st.y;

    float4 oa, ob;
    oa.x = (pva.x - st.x)*wa + gba + xva.x;
    oa.y = (pva.y - st.x)*wa + gba + xva.y;
    oa.z = (pva.z - st.x)*wa + gba + xva.z;
    oa.w = (pva.w - st.x)*wa + gba + xva.w;
    ob.x = (pvb.x - st.x)*wb + gbb + xvb.x;
    ob.y = (pvb.y - st.x)*wb + gbb + xvb.y;
    ob.z = (pvb.z - st.x)*wb + gbb + xvb.z;
    ob.w = (pvb.w - st.x)*wb + gbb + xvb.w;
    ((float4*)out)[ia] = oa;
    ((float4*)out)[ib] = ob;
}

// ======================= launch =============================================
extern "C" void kernel_launch(void* const* d_in, const int* in_sizes, int n_in,
                              void* d_out, int out_size)
{
    const float* x    = (const float*)d_in[0];
    const float* Wq   = (const float*)d_in[1];
    const float* bq   = (const float*)d_in[2];
    const float* Wk   = (const float*)d_in[3];
    const float* bk   = (const float*)d_in[4];
    const float* Wv   = (const float*)d_in[5];
    const float* bv   = (const float*)d_in[6];
    const float* Wo   = (const float*)d_in[7];
    const float* bo   = (const float*)d_in[8];
    const float* gn_w = (const float*)d_in[9];
    const float* gn_b = (const float*)d_in[10];
    float* out = (float*)d_out;

    wcvt_kernel<<<128, 256>>>(Wq, Wk, Wv, Wo);
    qkv_mma_kernel<<<dim3(NB*64, 3), 256>>>(x, bq, bk, bv);
    attn_mma_kernel<<<dim3(NB*NHD, NN/128), 128>>>();
    oproj_mma_kernel<<<NB*128, 256>>>(bo);
    gnapply_kernel<<<NB*NC*NN/4/512, 256>>>(x, gn_w, gn_b, out);
}

// round 13
// speedup vs baseline: 1.0004x; 1.0004x over previous
#include <cuda_runtime.h>
#include <cuda_fp16.h>
#include <cstdint>

#define NB 2
#define NC 128
#define NN 4096      // H*W
#define NHD 8        // heads
#define DH 16        // head dim
#define NG 8         // groupnorm groups
#define GN_EPS 1e-5f
#define CSCALE 0.36067376022224085f   // 0.25 * log2(e)

// ======================= PTX helpers (baseline sm_80+ features only) =======
__device__ __forceinline__ uint32_t smem_u32(const void* p) {
    uint32_t a;
    asm("{ .reg .u64 t; cvta.to.shared.u64 t, %1; cvt.u32.u64 %0, t; }" : "=r"(a) : "l"(p));
    return a;
}
__device__ __forceinline__ void ldsm_x4(uint32_t* r, uint32_t a) {
    asm volatile("ldmatrix.sync.aligned.m8n8.x4.shared.b16 {%0,%1,%2,%3}, [%4];"
        : "=r"(r[0]), "=r"(r[1]), "=r"(r[2]), "=r"(r[3]) : "r"(a));
}
__device__ __forceinline__ void ldsm_x4t(uint32_t* r, uint32_t a) {
    asm volatile("ldmatrix.sync.aligned.m8n8.x4.trans.shared.b16 {%0,%1,%2,%3}, [%4];"
        : "=r"(r[0]), "=r"(r[1]), "=r"(r[2]), "=r"(r[3]) : "r"(a));
}
__device__ __forceinline__ void mma_fp16(float* d, const uint32_t* a,
                                         const uint32_t* b, const float* c) {
    asm volatile("mma.sync.aligned.m16n8k16.row.col.f32.f16.f16.f32 "
        "{%0,%1,%2,%3},{%4,%5,%6,%7},{%8,%9},{%10,%11,%12,%13};"
        : "=f"(d[0]), "=f"(d[1]), "=f"(d[2]), "=f"(d[3])
        : "r"(a[0]), "r"(a[1]), "r"(a[2]), "r"(a[3]), "r"(b[0]), "r"(b[1]),
          "f"(c[0]), "f"(c[1]), "f"(c[2]), "f"(c[3]));
}
// f16-accumulator HMMA: D packed f16x2 {rows r | rows r+8}
__device__ __forceinline__ void mma_h16(uint32_t* d, const uint32_t* a, const uint32_t* b) {
    uint32_t z = 0u;
    asm volatile("mma.sync.aligned.m16n8k16.row.col.f16.f16.f16.f16 "
        "{%0,%1},{%2,%3,%4,%5},{%6,%7},{%8,%9};"
        : "=r"(d[0]), "=r"(d[1])
        : "r"(a[0]), "r"(a[1]), "r"(a[2]), "r"(a[3]), "r"(b[0]), "r"(b[1]),
          "r"(z), "r"(z));
}
__device__ __forceinline__ uint32_t ex2h2(uint32_t h) {
    asm("ex2.approx.f16x2 %0, %1;" : "=r"(h) : "r"(h)); return h;
}
__device__ __forceinline__ uint32_t hadd2u(uint32_t a, uint32_t b) {
    uint32_t d; asm("add.rn.f16x2 %0, %1, %2;" : "=r"(d) : "r"(a), "r"(b)); return d;
}
__device__ __forceinline__ uint32_t f2h2(float lo, float hi) {
    __half2 h = __floats2half2_rn(lo, hi);
    return *reinterpret_cast<uint32_t*>(&h);
}

// ======================= scratch =============================================
__device__ __half g_q  [NB*NHD*NN*DH];   // [b,h,n,d], pre-scaled by CSCALE
__device__ __half g_k  [NB*NHD*NN*DH];   // [b,h,n,d]
__device__ __half g_v  [NB*NHD*NN*DH];   // [b,h,n,d]
__device__ __half g_aoh[NB*NN*NC];       // attention out fp16, [b,n,c]
__device__ float  g_proj[NB*NC*NN];      // out-proj fp32, channel-major [b,c,n]
__device__ float2 g_part[NB*NG*64];      // GN partial (sum, sumsq) per token-chunk
__device__ __align__(16) __half g_wh[4*NC*NC];  // fp16 weights: Wq,Wk,Wv,Wo

// ======================= Kernel W: weight fp32 -> fp16 once =================
__global__ __launch_bounds__(256) void wcvt_kernel(
    const float* __restrict__ Wq, const float* __restrict__ Wk,
    const float* __restrict__ Wv, const float* __restrict__ Wo)
{
    int i = blockIdx.x * 256 + threadIdx.x;     // float2 units, 0..32767
    int m = i >> 13, o = i & 8191;
    const float* src = (m == 0) ? Wq : (m == 1) ? Wk : (m == 2) ? Wv : Wo;
    float2 v = ((const float2*)src)[o];
    *(uint32_t*)(g_wh + (size_t)m*16384 + o*2) = f2h2(v.x, v.y);
}

// ======================= Kernel A: QKV projection (256 threads) =============
// grid (NB*64, 3): 64 tokens x 128 outcols per CTA; 8 warps = 4 m-tiles x 2 halves.
__global__ __launch_bounds__(256) void qkv_mma_kernel(
    const float* __restrict__ x,
    const float* __restrict__ bq, const float* __restrict__ bk,
    const float* __restrict__ bv)
{
    __shared__ __align__(16) __half xs[64*136];
    __shared__ __align__(16) __half ws[128*72];
    __shared__ float bs[128];

    const int bi = blockIdx.x >> 6;
    const int n0 = (blockIdx.x & 63) * 64;
    const int m  = blockIdx.y;
    const int tid = threadIdx.x, lane = tid & 31, wid = tid >> 5;
    const int mt = wid & 3, gh = wid >> 2;

    const __half* __restrict__ wsrc = g_wh + (size_t)m*16384;
    const float* __restrict__ bias  = (m == 0) ? bq : (m == 1) ? bk : bv;
    __half* __restrict__ outp       = (m == 0) ? g_q : (m == 1) ? g_k : g_v;
    const float s = (m == 0) ? CSCALE : 1.f;

    if (tid < 128) bs[tid] = bias[tid];

    {   // x tile [c=128][n=64] -> xs[n][c] fp16 (256 threads: 32 cols each)
        const int row = tid & 63, ch = (tid >> 6) * 32;
        const float* xp = x + (size_t)(bi*NC + ch)*NN + n0 + row;
        #pragma unroll 4
        for (int cc = 0; cc < 32; cc += 2) {
            float a = xp[(size_t)cc*NN];
            float b = xp[(size_t)(cc+1)*NN];
            *(uint32_t*)(xs + row*136 + ch + cc) = f2h2(a, b);
        }
    }
    __syncthreads();

    uint32_t qa[8][4];   // warp's 16 token rows, all 8 k-steps
    {
        uint32_t base = smem_u32(xs) +
            ((uint32_t)(mt*16 + (lane & 15))*136 + ((lane >> 4) & 1)*8)*2;
        #pragma unroll
        for (int k = 0; k < 8; ++k) ldsm_x4(qa[k], base + (uint32_t)k*32);
    }

    float of[8][4];
    #pragma unroll
    for (int t = 0; t < 8; ++t)
        #pragma unroll
        for (int j = 0; j < 4; ++j) of[t][j] = 0.f;

    for (int ph = 0; ph < 2; ++ph) {
        __syncthreads();
        #pragma unroll
        for (int i = tid; i < 1024; i += 256) {    // fp16 weight copy
            int d = i >> 3, u = i & 7;
            *(uint4*)(ws + d*72 + u*8) = *(const uint4*)(wsrc + d*128 + ph*64 + u*8);
        }
        __syncthreads();
        #pragma unroll
        for (int kk = 0; kk < 4; ++kk) {
            const int k = ph*4 + kk;
            uint32_t bbase = smem_u32(ws) +
                ((uint32_t)(gh*64 + ((lane >> 4) & 1)*8 + (lane & 7))*72)*2 +
                (uint32_t)kk*32 + ((lane >> 3) & 1)*16;
            #pragma unroll
            for (int g = 0; g < 4; ++g) {
                uint32_t bb[4];
                ldsm_x4(bb, bbase + (uint32_t)g*16*72*2);
                mma_fp16(of[2*g],   qa[k], bb,     of[2*g]);
                mma_fp16(of[2*g+1], qa[k], bb + 2, of[2*g+1]);
            }
        }
    }

    const int r = mt*16 + (lane >> 2);
    #pragma unroll
    for (int nt = 0; nt < 8; ++nt) {
        int c0 = gh*64 + (nt >> 1)*16 + (nt & 1)*8 + (lane & 3)*2;
        int h = c0 >> 4, d = c0 & 15;
        __half* dst = outp + ((size_t)((bi*NHD + h)*NN) + n0 + r)*DH + d;
        *(uint32_t*)dst          = f2h2((of[nt][0]+bs[c0])*s, (of[nt][1]+bs[c0+1])*s);
        *(uint32_t*)(dst + 8*DH) = f2h2((of[nt][2]+bs[c0])*s, (of[nt][3]+bs[c0+1])*s);
    }
}

// ======================= Kernel B: HMMA flash attention (f16-acc, x4t V) ====
__global__ __launch_bounds__(128) void attn_mma_kernel()
{
    __shared__ __align__(16) __half qs[128*24];
    __shared__ __align__(16) __half ks[128*24];
    __shared__ __align__(16) __half vs[128*24];

    const int bh = blockIdx.x;
    const int n0 = blockIdx.y * 128;
    const int tid = threadIdx.x, lane = tid & 31, wid = tid >> 5;

    const __half* __restrict__ qg = g_q + (size_t)bh*NN*DH;
    const __half* __restrict__ kg = g_k + (size_t)bh*NN*DH;
    const __half* __restrict__ vg = g_v + (size_t)bh*NN*DH;

    {
        const uint4* q4 = (const uint4*)(qg + (size_t)(n0 + tid)*DH);
        *(uint4*)(qs + tid*24)     = q4[0];
        *(uint4*)(qs + tid*24 + 8) = q4[1];
    }
    uint4 pk0, pk1, pv0, pv1;
    {
        const uint4* kp = (const uint4*)(kg + (size_t)tid*DH);
        pk0 = kp[0]; pk1 = kp[1];
        const uint4* vp = (const uint4*)(vg + (size_t)tid*DH);
        pv0 = vp[0]; pv1 = vp[1];
    }
    __syncthreads();

    uint32_t qa[2][4];
    #pragma unroll
    for (int mt = 0; mt < 2; ++mt)
        ldsm_x4(qa[mt], smem_u32(qs) +
            ((uint32_t)(wid*32 + mt*16 + (lane & 15))*24 + ((lane >> 4) & 1)*8)*2);

    float of[2][2][4];
    #pragma unroll
    for (int a = 0; a < 2; ++a)
        #pragma unroll
        for (int b = 0; b < 2; ++b)
            #pragma unroll
            for (int c = 0; c < 4; ++c) of[a][b][c] = 0.f;
    float lf[4] = {0.f, 0.f, 0.f, 0.f};

    const uint32_t kaddr = smem_u32(ks) +
        (uint32_t)(((lane >> 4) & 1)*8 + (lane & 7))*48 + ((lane >> 3) & 1)*16;
    const uint32_t vaddr4 = smem_u32(vs) +
        (uint32_t)(lane & 15)*48 + ((lane >> 4) & 1)*16;

    for (int it = 0; it < 32; ++it) {
        __syncthreads();
        *(uint4*)(ks + tid*24)     = pk0;
        *(uint4*)(ks + tid*24 + 8) = pk1;
        *(uint4*)(vs + tid*24)     = pv0;
        *(uint4*)(vs + tid*24 + 8) = pv1;
        if (it + 1 < 32) {
            const int kt = (it + 1) * 128;
            const uint4* kp = (const uint4*)(kg + (size_t)(kt + tid)*DH);
            pk0 = kp[0]; pk1 = kp[1];
            const uint4* vp = (const uint4*)(vg + (size_t)(kt + tid)*DH);
            pv0 = vp[0]; pv1 = vp[1];
        }
        __syncthreads();

        uint32_t lh[4] = {0u, 0u, 0u, 0u};
        uint32_t kb[4];
        uint32_t scb[2][8];                 // ping-pong f16x2 scores
        ldsm_x4(kb, kaddr);
        mma_h16(scb[0]+0, qa[0], kb);
        mma_h16(scb[0]+2, qa[0], kb + 2);
        mma_h16(scb[0]+4, qa[1], kb);
        mma_h16(scb[0]+6, qa[1], kb + 2);

        #pragma unroll
        for (int k4 = 0; k4 < 8; ++k4) {
            const int cur = k4 & 1, nxt = cur ^ 1;
            if (k4 < 7) {                  // QK(k4+1) overlaps exp/PV(k4)
                ldsm_x4(kb, kaddr + (uint32_t)(k4+1)*768);
                mma_h16(scb[nxt]+0, qa[0], kb);
                mma_h16(scb[nxt]+2, qa[0], kb + 2);
                mma_h16(scb[nxt]+4, qa[1], kb);
                mma_h16(scb[nxt]+6, qa[1], kb + 2);
            }
            uint32_t vb[4];                // one x4t: {k0-7,k8-15} x {n0-7,n8-15}
            ldsm_x4t(vb, vaddr4 + (uint32_t)k4*768);
            #pragma unroll
            for (int mt = 0; mt < 2; ++mt) {
                uint32_t pa[4];
                pa[0] = ex2h2(scb[cur][mt*4+0]);
                pa[1] = ex2h2(scb[cur][mt*4+1]);
                pa[2] = ex2h2(scb[cur][mt*4+2]);
                pa[3] = ex2h2(scb[cur][mt*4+3]);
                lh[mt*2]   = hadd2u(lh[mt*2],   hadd2u(pa[0], pa[2]));
                lh[mt*2+1] = hadd2u(lh[mt*2+1], hadd2u(pa[1], pa[3]));
                mma_fp16(of[mt][0], pa, vb,     of[mt][0]);
                mma_fp16(of[mt][1], pa, vb + 2, of[mt][1]);
            }
        }
        #pragma unroll
        for (int i = 0; i < 4; ++i) {
            float2 f = __half22float2(*reinterpret_cast<__half2*>(&lh[i]));
            lf[i] += f.x + f.y;
        }
    }

    const int b = bh >> 3, h = bh & 7;
    #pragma unroll
    for (int mt = 0; mt < 2; ++mt) {
        #pragma unroll
        for (int rr = 0; rr < 2; ++rr) {
            float l = lf[mt*2 + rr];
            l += __shfl_xor_sync(0xffffffffu, l, 1);
            l += __shfl_xor_sync(0xffffffffu, l, 2);
            float inv = 1.f / l;
            int r = wid*32 + mt*16 + rr*8 + (lane >> 2);
            __half* dst = g_aoh + ((size_t)(b*NN) + n0 + r)*NC + h*16 + (lane & 3)*2;
            *(uint32_t*)dst       = f2h2(of[mt][0][rr*2]*inv, of[mt][0][rr*2+1]*inv);
            *(uint32_t*)(dst + 8) = f2h2(of[mt][1][rr*2]*inv, of[mt][1][rr*2+1]*inv);
        }
    }
}

// ======================= Kernel C: output projection (256 threads) ==========
// grid NB*128: CTA = (bi, 64-token chunk, 64-outcol half); 8 warps = 4 m x 2 q.
__global__ __launch_bounds__(256) void oproj_mma_kernel(const float* __restrict__ bo)
{
    __shared__ __align__(16) __half as_[64*136];
    __shared__ __align__(16) __half ws[64*136];
    __shared__ float bs[64];
    __shared__ float ws1[8][2], ws2[8][2];

    const int bi = blockIdx.x >> 7;
    const int rest = blockIdx.x & 127;
    const int chunk = rest >> 1;
    const int half = rest & 1;
    const int n0 = chunk * 64;
    const int tid = threadIdx.x, lane = tid & 31, wid = tid >> 5;
    const int mt = wid & 3, gh = wid >> 2;       // m-tile, 32-col quarter
    const __half* __restrict__ wsrc = g_wh + (size_t)3*16384 + (size_t)half*64*128;

    if (tid < 64) bs[tid] = bo[half*64 + tid];

    for (int idx = tid; idx < 64*64; idx += 256) {   // aoh tile (full K=128)
        int row = idx >> 6, u = idx & 63;
        uint32_t v = ((const uint32_t*)(g_aoh + ((size_t)(bi*NN) + n0 + row)*NC))[u];
        *(uint32_t*)(as_ + row*136 + u*2) = v;
    }
    #pragma unroll
    for (int i = tid; i < 1024; i += 256) {          // 64 weight rows x 128 k
        int d = i >> 4, u = i & 15;
        *(uint4*)(ws + d*136 + u*8) = ((const uint4*)wsrc)[d*16 + u];
    }
    __syncthreads();

    uint32_t qa[8][4];   // warp's 16 token rows
    {
        uint32_t base = smem_u32(as_) +
            ((uint32_t)(mt*16 + (lane & 15))*136 + ((lane >> 4) & 1)*8)*2;
        #pragma unroll
        for (int k = 0; k < 8; ++k) ldsm_x4(qa[k], base + (uint32_t)k*32);
    }

    float of[4][4];
    #pragma unroll
    for (int t = 0; t < 4; ++t)
        #pragma unroll
        for (int j = 0; j < 4; ++j) of[t][j] = 0.f;

    #pragma unroll
    for (int k = 0; k < 8; ++k) {
        uint32_t bbase = smem_u32(ws) +
            ((uint32_t)(gh*32 + ((lane >> 4) & 1)*8 + (lane & 7))*136)*2 +
            (uint32_t)k*32 + ((lane >> 3) & 1)*16;
        #pragma unroll
        for (int g = 0; g < 2; ++g) {
            uint32_t bb[4];
            ldsm_x4(bb, bbase + (uint32_t)g*16*136*2);
            mma_fp16(of[2*g],   qa[k], bb,     of[2*g]);
            mma_fp16(of[2*g+1], qa[k], bb + 2, of[2*g+1]);
        }
    }

    // epilogue: bias, store g_proj, per-group (sum,sumsq) for 2 local groups
    const int r = mt*16 + (lane >> 2);
    float gs1[2] = {0.f, 0.f}, gs2[2] = {0.f, 0.f};

    #pragma unroll
    for (int nt = 0; nt < 4; ++nt) {
        int c0l = gh*32 + (nt >> 1)*16 + (nt & 1)*8 + (lane & 3)*2;
        int c0 = half*64 + c0l;
        float v0 = of[nt][0] + bs[c0l];
        float v1 = of[nt][1] + bs[c0l+1];
        float v2 = of[nt][2] + bs[c0l];
        float v3 = of[nt][3] + bs[c0l+1];
        float* d0 = g_proj + (size_t)(bi*NC + c0)*NN + n0 + r;
        float* d1 = g_proj + (size_t)(bi*NC + c0 + 1)*NN + n0 + r;
        d0[0] = v0; d1[0] = v1; d0[8] = v2; d1[8] = v3;
        int gl = nt >> 1;
        gs1[gl] += (v0 + v1) + (v2 + v3);
        gs2[gl] += (v0*v0 + v1*v1) + (v2*v2 + v3*v3);
    }
    #pragma unroll
    for (int g = 0; g < 2; ++g) {
        float s1 = gs1[g], s2 = gs2[g];
        #pragma unroll
        for (int o = 16; o > 0; o >>= 1) {
            s1 += __shfl_xor_sync(0xffffffffu, s1, o);
            s2 += __shfl_xor_sync(0xffffffffu, s2, o);
        }
        if (lane == 0) { ws1[wid][g] = s1; ws2[wid][g] = s2; }
    }
    __syncthreads();
    if (tid < 4) {   // local group tid = gh_*2 + gl; warps gh_*4 + mt, mt 0..3
        int gh_ = tid >> 1, gl = tid & 1;
        float S1 = ws1[gh_*4+0][gl] + ws1[gh_*4+1][gl] + ws1[gh_*4+2][gl] + ws1[gh_*4+3][gl];
        float S2 = ws2[gh_*4+0][gl] + ws2[gh_*4+1][gl] + ws2[gh_*4+2][gl] + ws2[gh_*4+3][gl];
        g_part[(bi*NG + half*4 + tid)*64 + chunk] = make_float2(S1, S2);
    }
}

// ======================= Kernel E: GN apply + residual (MLP 4) ==============
__global__ __launch_bounds__(256) void gnapply_kernel(
    const float* __restrict__ x,
    const float* __restrict__ gn_w, const float* __restrict__ gn_b,
    float* __restrict__ out)
{
    __shared__ float2 st_s;
    const int tid = threadIdx.x;
    if (tid < 32) {
        int bg = blockIdx.x >> 5;            // 32 blocks per (b,g)
        float S1 = 0.f, S2 = 0.f;
        #pragma unroll
        for (int c = tid; c < 64; c += 32) {
            float2 pp = g_part[bg*64 + c];
            S1 += pp.x; S2 += pp.y;
        }
        #pragma unroll
        for (int o = 16; o > 0; o >>= 1) {
            S1 += __shfl_xor_sync(0xffffffffu, S1, o);
            S2 += __shfl_xor_sync(0xffffffffu, S2, o);
        }
        if (tid == 0) {
            const float invn = 1.f / (16.f * NN);
            float mean = S1 * invn;
            float var  = S2 * invn - mean*mean;
            st_s = make_float2(mean, rsqrtf(var + GN_EPS));
        }
    }

    int ia = blockIdx.x * 512 + tid;
    int ib = ia + 256;
    float4 pva = ((const float4*)g_proj)[ia];
    float4 xva = ((const float4*)x)[ia];
    float4 pvb = ((const float4*)g_proj)[ib];
    float4 xvb = ((const float4*)x)[ib];
    int ca = (ia >> 10) & 127, cb = (ib >> 10) & 127;
    float gwa = gn_w[ca], gba = gn_b[ca];
    float gwb = gn_w[cb], gbb = gn_b[cb];

    __syncthreads();
    float2 st = st_s;
    float wa = gwa * st.y, wb = gwb * st.y;

    float4 oa, ob;
    oa.x = (pva.x - st.x)*wa + gba + xva.x;
    oa.y = (pva.y - st.x)*wa + gba + xva.y;
    oa.z = (pva.z - st.x)*wa + gba + xva.z;
    oa.w = (pva.w - st.x)*wa + gba + xva.w;
    ob.x = (pvb.x - st.x)*wb + gbb + xvb.x;
    ob.y = (pvb.y - st.x)*wb + gbb + xvb.y;
    ob.z = (pvb.z - st.x)*wb + gbb + xvb.z;
    ob.w = (pvb.w - st.x)*wb + gbb + xvb.w;
    ((float4*)out)[ia] = oa;
    ((float4*)out)[ib] = ob;
}

// ======================= launch =============================================
extern "C" void kernel_launch(void* const* d_in, const int* in_sizes, int n_in,
                              void* d_out, int out_size)
{
    const float* x    = (const float*)d_in[0];
    const float* Wq   = (const float*)d_in[1];
    const float* bq   = (const float*)d_in[2];
    const float* Wk   = (const float*)d_in[3];
    const float* bk   = (const float*)d_in[4];
    const float* Wv   = (const float*)d_in[5];
    const float* bv   = (const float*)d_in[6];
    const float* Wo   = (const float*)d_in[7];
    const float* bo   = (const float*)d_in[8];
    const float* gn_w = (const float*)d_in[9];
    const float* gn_b = (const float*)d_in[10];
    float* out = (float*)d_out;

    wcvt_kernel<<<128, 256>>>(Wq, Wk, Wv, Wo);
    qkv_mma_kernel<<<dim3(NB*64, 3), 256>>>(x, bq, bk, bv);
    attn_mma_kernel<<<dim3(NB*NHD, NN/128), 128>>>();
    oproj_mma_kernel<<<NB*128, 256>>>(bo);
    gnapply_kernel<<<NB*NC*NN/4/512, 256>>>(x, gn_w, gn_b, out);
}

// round 14
// speedup vs baseline: 1.0515x; 1.0511x over previous
#include <cuda_runtime.h>
#include <cuda_fp16.h>
#include <cstdint>

#define NB 2
#define NC 128
#define NN 4096      // H*W
#define NHD 8        // heads
#define DH 16        // head dim
#define NG 8         // groupnorm groups
#define GN_EPS 1e-5f
#define CSCALE 0.36067376022224085f   // 0.25 * log2(e)

// ======================= PTX helpers (baseline sm_80+ features only) =======
__device__ __forceinline__ uint32_t smem_u32(const void* p) {
    uint32_t a;
    asm("{ .reg .u64 t; cvta.to.shared.u64 t, %1; cvt.u32.u64 %0, t; }" : "=r"(a) : "l"(p));
    return a;
}
__device__ __forceinline__ void ldsm_x4(uint32_t* r, uint32_t a) {
    asm volatile("ldmatrix.sync.aligned.m8n8.x4.shared.b16 {%0,%1,%2,%3}, [%4];"
        : "=r"(r[0]), "=r"(r[1]), "=r"(r[2]), "=r"(r[3]) : "r"(a));
}
__device__ __forceinline__ void ldsm_x4t(uint32_t* r, uint32_t a) {
    asm volatile("ldmatrix.sync.aligned.m8n8.x4.trans.shared.b16 {%0,%1,%2,%3}, [%4];"
        : "=r"(r[0]), "=r"(r[1]), "=r"(r[2]), "=r"(r[3]) : "r"(a));
}
__device__ __forceinline__ void mma_fp16(float* d, const uint32_t* a,
                                         const uint32_t* b, const float* c) {
    asm volatile("mma.sync.aligned.m16n8k16.row.col.f32.f16.f16.f32 "
        "{%0,%1,%2,%3},{%4,%5,%6,%7},{%8,%9},{%10,%11,%12,%13};"
        : "=f"(d[0]), "=f"(d[1]), "=f"(d[2]), "=f"(d[3])
        : "r"(a[0]), "r"(a[1]), "r"(a[2]), "r"(a[3]), "r"(b[0]), "r"(b[1]),
          "f"(c[0]), "f"(c[1]), "f"(c[2]), "f"(c[3]));
}
// f16-accumulator HMMA: D packed f16x2 {rows r | rows r+8}
__device__ __forceinline__ void mma_h16(uint32_t* d, const uint32_t* a, const uint32_t* b) {
    uint32_t z = 0u;
    asm volatile("mma.sync.aligned.m16n8k16.row.col.f16.f16.f16.f16 "
        "{%0,%1},{%2,%3,%4,%5},{%6,%7},{%8,%9};"
        : "=r"(d[0]), "=r"(d[1])
        : "r"(a[0]), "r"(a[1]), "r"(a[2]), "r"(a[3]), "r"(b[0]), "r"(b[1]),
          "r"(z), "r"(z));
}
__device__ __forceinline__ uint32_t ex2h2(uint32_t h) {
    asm("ex2.approx.f16x2 %0, %1;" : "=r"(h) : "r"(h)); return h;
}
__device__ __forceinline__ uint32_t hadd2u(uint32_t a, uint32_t b) {
    uint32_t d; asm("add.rn.f16x2 %0, %1, %2;" : "=r"(d) : "r"(a), "r"(b)); return d;
}
__device__ __forceinline__ uint32_t f2h2(float lo, float hi) {
    __half2 h = __floats2half2_rn(lo, hi);
    return *reinterpret_cast<uint32_t*>(&h);
}

// ======================= scratch =============================================
__device__ __half g_q  [NB*NHD*NN*DH];   // [b,h,n,d], pre-scaled by CSCALE
__device__ __half g_k  [NB*NHD*NN*DH];   // [b,h,n,d]
__device__ __half g_v  [NB*NHD*NN*DH];   // [b,h,n,d]
__device__ __half g_aoh[NB*NN*NC];       // attention out fp16, [b,n,c]
__device__ float  g_proj[NB*NC*NN];      // out-proj fp32, channel-major [b,c,n]
__device__ float2 g_part[NB*NG*64];      // GN partial (sum, sumsq) per token-chunk
__device__ __align__(16) __half g_wh[4*NC*NC];  // fp16 weights: Wq,Wk,Wv,Wo

// ======================= Kernel W: weight fp32 -> fp16 once =================
__global__ __launch_bounds__(256) void wcvt_kernel(
    const float* __restrict__ Wq, const float* __restrict__ Wk,
    const float* __restrict__ Wv, const float* __restrict__ Wo)
{
    int i = blockIdx.x * 256 + threadIdx.x;     // float2 units, 0..32767
    int m = i >> 13, o = i & 8191;
    const float* src = (m == 0) ? Wq : (m == 1) ? Wk : (m == 2) ? Wv : Wo;
    float2 v = ((const float2*)src)[o];
    *(uint32_t*)(g_wh + (size_t)m*16384 + o*2) = f2h2(v.x, v.y);
}

// ======================= Kernel A: QKV projection (R10 shape, 128 thr) ======
__global__ __launch_bounds__(128) void qkv_mma_kernel(
    const float* __restrict__ x,
    const float* __restrict__ bq, const float* __restrict__ bk,
    const float* __restrict__ bv)
{
    __shared__ __align__(16) __half xs[64*136];
    __shared__ __align__(16) __half ws[128*72];
    __shared__ float bs[128];

    const int bi = blockIdx.x >> 6;
    const int n0 = (blockIdx.x & 63) * 64;
    const int m  = blockIdx.y;
    const int tid = threadIdx.x, lane = tid & 31, wid = tid >> 5;

    const __half* __restrict__ wsrc = g_wh + (size_t)m*16384;
    const float* __restrict__ bias  = (m == 0) ? bq : (m == 1) ? bk : bv;
    __half* __restrict__ outp       = (m == 0) ? g_q : (m == 1) ? g_k : g_v;
    const float s = (m == 0) ? CSCALE : 1.f;

    bs[tid] = bias[tid];

    {   // x tile [c=128][n=64] -> xs[n][c] fp16
        const int row = tid & 63, ch = (tid >> 6) * 64;
        const float* xp = x + (size_t)(bi*NC + ch)*NN + n0 + row;
        #pragma unroll 8
        for (int cc = 0; cc < 64; cc += 2) {
            float a = xp[(size_t)cc*NN];
            float b = xp[(size_t)(cc+1)*NN];
            *(uint32_t*)(xs + row*136 + ch + cc) = f2h2(a, b);
        }
    }
    __syncthreads();

    uint32_t qa[8][4];
    {
        uint32_t base = smem_u32(xs) +
            ((uint32_t)(wid*16 + (lane & 15))*136 + ((lane >> 4) & 1)*8)*2;
        #pragma unroll
        for (int k = 0; k < 8; ++k) ldsm_x4(qa[k], base + (uint32_t)k*32);
    }

    float of[16][4];
    #pragma unroll
    for (int t = 0; t < 16; ++t)
        #pragma unroll
        for (int j = 0; j < 4; ++j) of[t][j] = 0.f;

    for (int ph = 0; ph < 2; ++ph) {
        __syncthreads();
        #pragma unroll
        for (int i = tid; i < 1024; i += 128) {    // fp16 weight copy
            int d = i >> 3, u = i & 7;
            *(uint4*)(ws + d*72 + u*8) = *(const uint4*)(wsrc + d*128 + ph*64 + u*8);
        }
        __syncthreads();
        #pragma unroll
        for (int kk = 0; kk < 4; ++kk) {
            const int k = ph*4 + kk;
            uint32_t bbase = smem_u32(ws) +
                ((uint32_t)(((lane >> 4) & 1)*8 + (lane & 7))*72)*2 +
                (uint32_t)kk*32 + ((lane >> 3) & 1)*16;
            #pragma unroll
            for (int g = 0; g < 8; ++g) {
                uint32_t bb[4];
                ldsm_x4(bb, bbase + (uint32_t)g*16*72*2);
                mma_fp16(of[2*g],   qa[k], bb,     of[2*g]);
                mma_fp16(of[2*g+1], qa[k], bb + 2, of[2*g+1]);
            }
        }
    }

    const int r = wid*16 + (lane >> 2);
    #pragma unroll
    for (int nt = 0; nt < 16; ++nt) {
        int c0 = nt*8 + (lane & 3)*2;
        int h = c0 >> 4, d = c0 & 15;
        __half* dst = outp + ((size_t)((bi*NHD + h)*NN) + n0 + r)*DH + d;
        *(uint32_t*)dst          = f2h2((of[nt][0]+bs[c0])*s, (of[nt][1]+bs[c0+1])*s);
        *(uint32_t*)(dst + 8*DH) = f2h2((of[nt][2]+bs[c0])*s, (of[nt][3]+bs[c0+1])*s);
    }
}

// ======================= Kernel B: HMMA flash attention (f16-acc, x4t V) ====
__global__ __launch_bounds__(128) void attn_mma_kernel()
{
    __shared__ __align__(16) __half qs[128*24];
    __shared__ __align__(16) __half ks[128*24];
    __shared__ __align__(16) __half vs[128*24];

    const int bh = blockIdx.x;
    const int n0 = blockIdx.y * 128;
    const int tid = threadIdx.x, lane = tid & 31, wid = tid >> 5;

    const __half* __restrict__ qg = g_q + (size_t)bh*NN*DH;
    const __half* __restrict__ kg = g_k + (size_t)bh*NN*DH;
    const __half* __restrict__ vg = g_v + (size_t)bh*NN*DH;

    {
        const uint4* q4 = (const uint4*)(qg + (size_t)(n0 + tid)*DH);
        *(uint4*)(qs + tid*24)     = q4[0];
        *(uint4*)(qs + tid*24 + 8) = q4[1];
    }
    uint4 pk0, pk1, pv0, pv1;
    {
        const uint4* kp = (const uint4*)(kg + (size_t)tid*DH);
        pk0 = kp[0]; pk1 = kp[1];
        const uint4* vp = (const uint4*)(vg + (size_t)tid*DH);
        pv0 = vp[0]; pv1 = vp[1];
    }
    __syncthreads();

    uint32_t qa[2][4];
    #pragma unroll
    for (int mt = 0; mt < 2; ++mt)
        ldsm_x4(qa[mt], smem_u32(qs) +
            ((uint32_t)(wid*32 + mt*16 + (lane & 15))*24 + ((lane >> 4) & 1)*8)*2);

    float of[2][2][4];
    #pragma unroll
    for (int a = 0; a < 2; ++a)
        #pragma unroll
        for (int b = 0; b < 2; ++b)
            #pragma unroll
            for (int c = 0; c < 4; ++c) of[a][b][c] = 0.f;
    float lf[4] = {0.f, 0.f, 0.f, 0.f};

    const uint32_t kaddr = smem_u32(ks) +
        (uint32_t)(((lane >> 4) & 1)*8 + (lane & 7))*48 + ((lane >> 3) & 1)*16;
    const uint32_t vaddr4 = smem_u32(vs) +
        (uint32_t)(lane & 15)*48 + ((lane >> 4) & 1)*16;

    for (int it = 0; it < 32; ++it) {
        __syncthreads();
        *(uint4*)(ks + tid*24)     = pk0;
        *(uint4*)(ks + tid*24 + 8) = pk1;
        *(uint4*)(vs + tid*24)     = pv0;
        *(uint4*)(vs + tid*24 + 8) = pv1;
        if (it + 1 < 32) {
            const int kt = (it + 1) * 128;
            const uint4* kp = (const uint4*)(kg + (size_t)(kt + tid)*DH);
            pk0 = kp[0]; pk1 = kp[1];
            const uint4* vp = (const uint4*)(vg + (size_t)(kt + tid)*DH);
            pv0 = vp[0]; pv1 = vp[1];
        }
        __syncthreads();

        uint32_t lh[4] = {0u, 0u, 0u, 0u};
        uint32_t kb[4];
        uint32_t scb[2][8];                 // ping-pong f16x2 scores
        ldsm_x4(kb, kaddr);
        mma_h16(scb[0]+0, qa[0], kb);
        mma_h16(scb[0]+2, qa[0], kb + 2);
        mma_h16(scb[0]+4, qa[1], kb);
        mma_h16(scb[0]+6, qa[1], kb + 2);

        #pragma unroll
        for (int k4 = 0; k4 < 8; ++k4) {
            const int cur = k4 & 1, nxt = cur ^ 1;
            if (k4 < 7) {                  // QK(k4+1) overlaps exp/PV(k4)
                ldsm_x4(kb, kaddr + (uint32_t)(k4+1)*768);
                mma_h16(scb[nxt]+0, qa[0], kb);
                mma_h16(scb[nxt]+2, qa[0], kb + 2);
                mma_h16(scb[nxt]+4, qa[1], kb);
                mma_h16(scb[nxt]+6, qa[1], kb + 2);
            }
            uint32_t vb[4];                // one x4t: {k0-7,k8-15} x {n0-7,n8-15}
            ldsm_x4t(vb, vaddr4 + (uint32_t)k4*768);
            #pragma unroll
            for (int mt = 0; mt < 2; ++mt) {
                uint32_t pa[4];
                pa[0] = ex2h2(scb[cur][mt*4+0]);
                pa[1] = ex2h2(scb[cur][mt*4+1]);
                pa[2] = ex2h2(scb[cur][mt*4+2]);
                pa[3] = ex2h2(scb[cur][mt*4+3]);
                lh[mt*2]   = hadd2u(lh[mt*2],   hadd2u(pa[0], pa[2]));
                lh[mt*2+1] = hadd2u(lh[mt*2+1], hadd2u(pa[1], pa[3]));
                mma_fp16(of[mt][0], pa, vb,     of[mt][0]);
                mma_fp16(of[mt][1], pa, vb + 2, of[mt][1]);
            }
        }
        #pragma unroll
        for (int i = 0; i < 4; ++i) {
            float2 f = __half22float2(*reinterpret_cast<__half2*>(&lh[i]));
            lf[i] += f.x + f.y;
        }
    }

    const int b = bh >> 3, h = bh & 7;
    #pragma unroll
    for (int mt = 0; mt < 2; ++mt) {
        #pragma unroll
        for (int rr = 0; rr < 2; ++rr) {
            float l = lf[mt*2 + rr];
            l += __shfl_xor_sync(0xffffffffu, l, 1);
            l += __shfl_xor_sync(0xffffffffu, l, 2);
            float inv = 1.f / l;
            int r = wid*32 + mt*16 + rr*8 + (lane >> 2);
            __half* dst = g_aoh + ((size_t)(b*NN) + n0 + r)*NC + h*16 + (lane & 3)*2;
            *(uint32_t*)dst       = f2h2(of[mt][0][rr*2]*inv, of[mt][0][rr*2+1]*inv);
            *(uint32_t*)(dst + 8) = f2h2(of[mt][1][rr*2]*inv, of[mt][1][rr*2+1]*inv);
        }
    }
}

// ======================= Kernel C: oproj (col-split, coalesced epilogue) ====
// grid NB*128: CTA = (bi, 64-token chunk, 64-outcol half). Fragments go to
// smem [c][n] (stride 68 floats, float4-aligned, conflict-free), then
// coalesced 256B-row stores to channel-major g_proj.
__global__ __launch_bounds__(128) void oproj_mma_kernel(const float* __restrict__ bo)
{
    __shared__ __align__(16) __half as_[64*136];   // aoh tile; reused as os[]
    __shared__ __align__(16) __half ws[64*136];
    __shared__ float bs[64];
    __shared__ float ws1[4][4], ws2[4][4];
    float* os = (float*)as_;                       // 64*68 floats = 17408B fits

    const int bi = blockIdx.x >> 7;
    const int rest = blockIdx.x & 127;
    const int chunk = rest >> 1;
    const int half = rest & 1;
    const int n0 = chunk * 64;
    const int tid = threadIdx.x, lane = tid & 31, wid = tid >> 5;
    const __half* __restrict__ wsrc = g_wh + (size_t)3*16384 + (size_t)half*64*128;

    if (tid < 64) bs[tid] = bo[half*64 + tid];

    for (int idx = tid; idx < 64*64; idx += 128) {   // aoh tile (full K=128)
        int row = idx >> 6, u = idx & 63;
        uint32_t v = ((const uint32_t*)(g_aoh + ((size_t)(bi*NN) + n0 + row)*NC))[u];
        *(uint32_t*)(as_ + row*136 + u*2) = v;
    }
    #pragma unroll
    for (int i = tid; i < 1024; i += 128) {          // 64 weight rows x 128 k
        int d = i >> 4, u = i & 15;
        *(uint4*)(ws + d*136 + u*8) = ((const uint4*)wsrc)[d*16 + u];
    }
    __syncthreads();

    uint32_t qa[8][4];   // warp's 16 token rows
    {
        uint32_t base = smem_u32(as_) +
            ((uint32_t)(wid*16 + (lane & 15))*136 + ((lane >> 4) & 1)*8)*2;
        #pragma unroll
        for (int k = 0; k < 8; ++k) ldsm_x4(qa[k], base + (uint32_t)k*32);
    }

    float of[8][4];
    #pragma unroll
    for (int t = 0; t < 8; ++t)
        #pragma unroll
        for (int j = 0; j < 4; ++j) of[t][j] = 0.f;

    #pragma unroll
    for (int k = 0; k < 8; ++k) {
        uint32_t bbase = smem_u32(ws) +
            ((uint32_t)(((lane >> 4) & 1)*8 + (lane & 7))*136)*2 +
            (uint32_t)k*32 + ((lane >> 3) & 1)*16;
        #pragma unroll
        for (int g = 0; g < 4; ++g) {
            uint32_t bb[4];
            ldsm_x4(bb, bbase + (uint32_t)g*16*136*2);
            mma_fp16(of[2*g],   qa[k], bb,     of[2*g]);
            mma_fp16(of[2*g+1], qa[k], bb + 2, of[2*g+1]);
        }
    }
    __syncthreads();     // everyone done reading as_/ws; os overlay is now safe

    // epilogue 1: bias + GN partials + fragment -> os[c][n] (stride 68)
    const int r = wid*16 + (lane >> 2);
    float gs1[4], gs2[4];
    #pragma unroll
    for (int g = 0; g < 4; ++g) { gs1[g] = 0.f; gs2[g] = 0.f; }

    #pragma unroll
    for (int nt = 0; nt < 8; ++nt) {
        int c0l = nt*8 + (lane & 3)*2;
        float v0 = of[nt][0] + bs[c0l];
        float v1 = of[nt][1] + bs[c0l+1];
        float v2 = of[nt][2] + bs[c0l];
        float v3 = of[nt][3] + bs[c0l+1];
        os[c0l*68 + r]         = v0;
        os[(c0l+1)*68 + r]     = v1;
        os[c0l*68 + r + 8]     = v2;
        os[(c0l+1)*68 + r + 8] = v3;
        int gl = nt >> 1;
        gs1[gl] += (v0 + v1) + (v2 + v3);
        gs2[gl] += (v0*v0 + v1*v1) + (v2*v2 + v3*v3);
    }
    #pragma unroll
    for (int g = 0; g < 4; ++g) {
        float s1 = gs1[g], s2 = gs2[g];
        #pragma unroll
        for (int o = 16; o > 0; o >>= 1) {
            s1 += __shfl_xor_sync(0xffffffffu, s1, o);
            s2 += __shfl_xor_sync(0xffffffffu, s2, o);
        }
        if (lane == 0) { ws1[wid][g] = s1; ws2[wid][g] = s2; }
    }
    __syncthreads();
    if (tid < 4) {
        float S1 = ws1[0][tid] + ws1[1][tid] + ws1[2][tid] + ws1[3][tid];
        float S2 = ws2[0][tid] + ws2[1][tid] + ws2[2][tid] + ws2[3][tid];
        g_part[(bi*NG + half*4 + tid)*64 + chunk] = make_float2(S1, S2);
    }

    // epilogue 2: coalesced stores — each channel row is 256B contiguous
    #pragma unroll
    for (int i = tid; i < 1024; i += 128) {
        int c = i >> 4, u = i & 15;
        float4 v = *(const float4*)(os + c*68 + u*4);
        *(float4*)(g_proj + (size_t)(bi*NC + half*64 + c)*NN + n0 + u*4) = v;
    }
}

// ======================= Kernel E: GN apply + residual (MLP 4) ==============
__global__ __launch_bounds__(256) void gnapply_kernel(
    const float* __restrict__ x,
    const float* __restrict__ gn_w, const float* __restrict__ gn_b,
    float* __restrict__ out)
{
    __shared__ float2 st_s;
    const int tid = threadIdx.x;
    if (tid < 32) {
        int bg = blockIdx.x >> 5;            // 32 blocks per (b,g)
        float S1 = 0.f, S2 = 0.f;
        #pragma unroll
        for (int c = tid; c < 64; c += 32) {
            float2 pp = g_part[bg*64 + c];
            S1 += pp.x; S2 += pp.y;
        }
        #pragma unroll
        for (int o = 16; o > 0; o >>= 1) {
            S1 += __shfl_xor_sync(0xffffffffu, S1, o);
            S2 += __shfl_xor_sync(0xffffffffu, S2, o);
        }
        if (tid == 0) {
            const float invn = 1.f / (16.f * NN);
            float mean = S1 * invn;
            float var  = S2 * invn - mean*mean;
            st_s = make_float2(mean, rsqrtf(var + GN_EPS));
        }
    }

    int ia = blockIdx.x * 512 + tid;
    int ib = ia + 256;
    float4 pva = ((const float4*)g_proj)[ia];
    float4 xva = ((const float4*)x)[ia];
    float4 pvb = ((const float4*)g_proj)[ib];
    float4 xvb = ((const float4*)x)[ib];
    int ca = (ia >> 10) & 127, cb = (ib >> 10) & 127;
    float gwa = gn_w[ca], gba = gn_b[ca];
    float gwb = gn_w[cb], gbb = gn_b[cb];

    __syncthreads();
    float2 st = st_s;
    float wa = gwa * st.y, wb = gwb * st.y;

    float4 oa, ob;
    oa.x = (pva.x - st.x)*wa + gba + xva.x;
    oa.y = (pva.y - st.x)*wa + gba + xva.y;
    oa.z = (pva.z - st.x)*wa + gba + xva.z;
    oa.w = (pva.w - st.x)*wa + gba + xva.w;
    ob.x = (pvb.x - st.x)*wb + gbb + xvb.x;
    ob.y = (pvb.y - st.x)*wb + gbb + xvb.y;
    ob.z = (pvb.z - st.x)*wb + gbb + xvb.z;
    ob.w = (pvb.w - st.x)*wb + gbb + xvb.w;
    ((float4*)out)[ia] = oa;
    ((float4*)out)[ib] = ob;
}

// ======================= launch =============================================
extern "C" void kernel_launch(void* const* d_in, const int* in_sizes, int n_in,
                              void* d_out, int out_size)
{
    const float* x    = (const float*)d_in[0];
    const float* Wq   = (const float*)d_in[1];
    const float* bq   = (const float*)d_in[2];
    const float* Wk   = (const float*)d_in[3];
    const float* bk   = (const float*)d_in[4];
    const float* Wv   = (const float*)d_in[5];
    const float* bv   = (const float*)d_in[6];
    const float* Wo   = (const float*)d_in[7];
    const float* bo   = (const float*)d_in[8];
    const float* gn_w = (const float*)d_in[9];
    const float* gn_b = (const float*)d_in[10];
    float* out = (float*)d_out;

    wcvt_kernel<<<128, 256>>>(Wq, Wk, Wv, Wo);
    qkv_mma_kernel<<<dim3(NB*64, 3), 128>>>(x, bq, bk, bv);
    attn_mma_kernel<<<dim3(NB*NHD, NN/128), 128>>>();
    oproj_mma_kernel<<<NB*128, 128>>>(bo);
    gnapply_kernel<<<NB*NC*NN/4/512, 256>>>(x, gn_w, gn_b, out);
}

// round 15
// speedup vs baseline: 1.0856x; 1.0324x over previous
#include <cuda_runtime.h>
#include <cuda_fp16.h>
#include <cstdint>

#define NB 2
#define NC 128
#define NN 4096      // H*W
#define NHD 8        // heads
#define DH 16        // head dim
#define NG 8         // groupnorm groups
#define GN_EPS 1e-5f
#define CSCALE 0.36067376022224085f   // 0.25 * log2(e)

// ======================= PTX helpers (baseline sm_80+ features only) =======
__device__ __forceinline__ uint32_t smem_u32(const void* p) {
    uint32_t a;
    asm("{ .reg .u64 t; cvta.to.shared.u64 t, %1; cvt.u32.u64 %0, t; }" : "=r"(a) : "l"(p));
    return a;
}
__device__ __forceinline__ void ldsm_x4(uint32_t* r, uint32_t a) {
    asm volatile("ldmatrix.sync.aligned.m8n8.x4.shared.b16 {%0,%1,%2,%3}, [%4];"
        : "=r"(r[0]), "=r"(r[1]), "=r"(r[2]), "=r"(r[3]) : "r"(a));
}
__device__ __forceinline__ void ldsm_x4t(uint32_t* r, uint32_t a) {
    asm volatile("ldmatrix.sync.aligned.m8n8.x4.trans.shared.b16 {%0,%1,%2,%3}, [%4];"
        : "=r"(r[0]), "=r"(r[1]), "=r"(r[2]), "=r"(r[3]) : "r"(a));
}
__device__ __forceinline__ void mma_fp16(float* d, const uint32_t* a,
                                         const uint32_t* b, const float* c) {
    asm volatile("mma.sync.aligned.m16n8k16.row.col.f32.f16.f16.f32 "
        "{%0,%1,%2,%3},{%4,%5,%6,%7},{%8,%9},{%10,%11,%12,%13};"
        : "=f"(d[0]), "=f"(d[1]), "=f"(d[2]), "=f"(d[3])
        : "r"(a[0]), "r"(a[1]), "r"(a[2]), "r"(a[3]), "r"(b[0]), "r"(b[1]),
          "f"(c[0]), "f"(c[1]), "f"(c[2]), "f"(c[3]));
}
// f16-accumulator HMMA: D packed f16x2 {rows r | rows r+8}
__device__ __forceinline__ void mma_h16(uint32_t* d, const uint32_t* a, const uint32_t* b) {
    uint32_t z = 0u;
    asm volatile("mma.sync.aligned.m16n8k16.row.col.f16.f16.f16.f16 "
        "{%0,%1},{%2,%3,%4,%5},{%6,%7},{%8,%9};"
        : "=r"(d[0]), "=r"(d[1])
        : "r"(a[0]), "r"(a[1]), "r"(a[2]), "r"(a[3]), "r"(b[0]), "r"(b[1]),
          "r"(z), "r"(z));
}
__device__ __forceinline__ uint32_t ex2h2(uint32_t h) {
    asm("ex2.approx.f16x2 %0, %1;" : "=r"(h) : "r"(h)); return h;
}
__device__ __forceinline__ uint32_t hadd2u(uint32_t a, uint32_t b) {
    uint32_t d; asm("add.rn.f16x2 %0, %1, %2;" : "=r"(d) : "r"(a), "r"(b)); return d;
}
__device__ __forceinline__ uint32_t f2h2(float lo, float hi) {
    __half2 h = __floats2half2_rn(lo, hi);
    return *reinterpret_cast<uint32_t*>(&h);
}

// ======================= scratch =============================================
__device__ __half g_q  [NB*NHD*NN*DH];   // [b,h,n,d], pre-scaled by CSCALE
__device__ __half g_k  [NB*NHD*NN*DH];   // [b,h,n,d]
__device__ __half g_v  [NB*NHD*NN*DH];   // [b,h,n,d]
__device__ __half g_aoh[NB*NN*NC];       // attention out fp16, [b,n,c]
__device__ float  g_proj[NB*NC*NN];      // out-proj fp32, channel-major [b,c,n]
__device__ float2 g_part[NB*NG*64];      // GN partial (sum, sumsq) per token-chunk
__device__ __align__(16) __half g_wh[4*NC*NC];  // fp16 weights: Wq,Wk,Wv,Wo

// ======================= Kernel W: weight fp32 -> fp16 once =================
__global__ __launch_bounds__(256) void wcvt_kernel(
    const float* __restrict__ Wq, const float* __restrict__ Wk,
    const float* __restrict__ Wv, const float* __restrict__ Wo)
{
    int i = blockIdx.x * 256 + threadIdx.x;     // float2 units, 0..32767
    int m = i >> 13, o = i & 8191;
    const float* src = (m == 0) ? Wq : (m == 1) ? Wk : (m == 2) ? Wv : Wo;
    float2 v = ((const float2*)src)[o];
    *(uint32_t*)(g_wh + (size_t)m*16384 + o*2) = f2h2(v.x, v.y);
}

// ======================= Kernel A: QKV projection (R10 shape, 128 thr) ======
__global__ __launch_bounds__(128) void qkv_mma_kernel(
    const float* __restrict__ x,
    const float* __restrict__ bq, const float* __restrict__ bk,
    const float* __restrict__ bv)
{
    __shared__ __align__(16) __half xs[64*136];
    __shared__ __align__(16) __half ws[128*72];
    __shared__ float bs[128];

    const int bi = blockIdx.x >> 6;
    const int n0 = (blockIdx.x & 63) * 64;
    const int m  = blockIdx.y;
    const int tid = threadIdx.x, lane = tid & 31, wid = tid >> 5;

    const __half* __restrict__ wsrc = g_wh + (size_t)m*16384;
    const float* __restrict__ bias  = (m == 0) ? bq : (m == 1) ? bk : bv;
    __half* __restrict__ outp       = (m == 0) ? g_q : (m == 1) ? g_k : g_v;
    const float s = (m == 0) ? CSCALE : 1.f;

    bs[tid] = bias[tid];

    {   // x tile [c=128][n=64] -> xs[n][c] fp16
        const int row = tid & 63, ch = (tid >> 6) * 64;
        const float* xp = x + (size_t)(bi*NC + ch)*NN + n0 + row;
        #pragma unroll 8
        for (int cc = 0; cc < 64; cc += 2) {
            float a = xp[(size_t)cc*NN];
            float b = xp[(size_t)(cc+1)*NN];
            *(uint32_t*)(xs + row*136 + ch + cc) = f2h2(a, b);
        }
    }
    __syncthreads();

    uint32_t qa[8][4];
    {
        uint32_t base = smem_u32(xs) +
            ((uint32_t)(wid*16 + (lane & 15))*136 + ((lane >> 4) & 1)*8)*2;
        #pragma unroll
        for (int k = 0; k < 8; ++k) ldsm_x4(qa[k], base + (uint32_t)k*32);
    }

    float of[16][4];
    #pragma unroll
    for (int t = 0; t < 16; ++t)
        #pragma unroll
        for (int j = 0; j < 4; ++j) of[t][j] = 0.f;

    for (int ph = 0; ph < 2; ++ph) {
        __syncthreads();
        #pragma unroll
        for (int i = tid; i < 1024; i += 128) {    // fp16 weight copy
            int d = i >> 3, u = i & 7;
            *(uint4*)(ws + d*72 + u*8) = *(const uint4*)(wsrc + d*128 + ph*64 + u*8);
        }
        __syncthreads();
        #pragma unroll
        for (int kk = 0; kk < 4; ++kk) {
            const int k = ph*4 + kk;
            uint32_t bbase = smem_u32(ws) +
                ((uint32_t)(((lane >> 4) & 1)*8 + (lane & 7))*72)*2 +
                (uint32_t)kk*32 + ((lane >> 3) & 1)*16;
            #pragma unroll
            for (int g = 0; g < 8; ++g) {
                uint32_t bb[4];
                ldsm_x4(bb, bbase + (uint32_t)g*16*72*2);
                mma_fp16(of[2*g],   qa[k], bb,     of[2*g]);
                mma_fp16(of[2*g+1], qa[k], bb + 2, of[2*g+1]);
            }
        }
    }

    const int r = wid*16 + (lane >> 2);
    #pragma unroll
    for (int nt = 0; nt < 16; ++nt) {
        int c0 = nt*8 + (lane & 3)*2;
        int h = c0 >> 4, d = c0 & 15;
        __half* dst = outp + ((size_t)((bi*NHD + h)*NN) + n0 + r)*DH + d;
        *(uint32_t*)dst          = f2h2((of[nt][0]+bs[c0])*s, (of[nt][1]+bs[c0+1])*s);
        *(uint32_t*)(dst + 8*DH) = f2h2((of[nt][2]+bs[c0])*s, (of[nt][3]+bs[c0+1])*s);
    }
}

// ======================= Kernel B: HMMA flash attention (double-buffered) ===
// One __syncthreads per 128-key tile: stage buf[it&1], prefetch it+1, sync,
// compute. Write-after-read across buffers is safe (reads of buf b at iter
// i-2 complete before sync(i-2) < stage writes at iter i).
__global__ __launch_bounds__(128) void attn_mma_kernel()
{
    __shared__ __align__(16) __half qs[128*24];
    __shared__ __align__(16) __half ks[2*128*24];
    __shared__ __align__(16) __half vs[2*128*24];

    const int bh = blockIdx.x;
    const int n0 = blockIdx.y * 128;
    const int tid = threadIdx.x, lane = tid & 31, wid = tid >> 5;

    const __half* __restrict__ qg = g_q + (size_t)bh*NN*DH;
    const __half* __restrict__ kg = g_k + (size_t)bh*NN*DH;
    const __half* __restrict__ vg = g_v + (size_t)bh*NN*DH;

    {
        const uint4* q4 = (const uint4*)(qg + (size_t)(n0 + tid)*DH);
        *(uint4*)(qs + tid*24)     = q4[0];
        *(uint4*)(qs + tid*24 + 8) = q4[1];
    }
    uint4 pk0, pk1, pv0, pv1;
    {
        const uint4* kp = (const uint4*)(kg + (size_t)tid*DH);
        pk0 = kp[0]; pk1 = kp[1];
        const uint4* vp = (const uint4*)(vg + (size_t)tid*DH);
        pv0 = vp[0]; pv1 = vp[1];
    }
    __syncthreads();

    uint32_t qa[2][4];
    #pragma unroll
    for (int mt = 0; mt < 2; ++mt)
        ldsm_x4(qa[mt], smem_u32(qs) +
            ((uint32_t)(wid*32 + mt*16 + (lane & 15))*24 + ((lane >> 4) & 1)*8)*2);

    float of[2][2][4];
    #pragma unroll
    for (int a = 0; a < 2; ++a)
        #pragma unroll
        for (int b = 0; b < 2; ++b)
            #pragma unroll
            for (int c = 0; c < 4; ++c) of[a][b][c] = 0.f;
    float lf[4] = {0.f, 0.f, 0.f, 0.f};

    const uint32_t kaddr = smem_u32(ks) +
        (uint32_t)(((lane >> 4) & 1)*8 + (lane & 7))*48 + ((lane >> 3) & 1)*16;
    const uint32_t vaddr4 = smem_u32(vs) +
        (uint32_t)(lane & 15)*48 + ((lane >> 4) & 1)*16;

    for (int it = 0; it < 32; ++it) {
        const uint32_t boff = (uint32_t)(it & 1) * 6144;   // bytes per buffer
        __half* ksb = ks + (it & 1)*128*24;
        __half* vsb = vs + (it & 1)*128*24;
        *(uint4*)(ksb + tid*24)     = pk0;
        *(uint4*)(ksb + tid*24 + 8) = pk1;
        *(uint4*)(vsb + tid*24)     = pv0;
        *(uint4*)(vsb + tid*24 + 8) = pv1;
        if (it + 1 < 32) {
            const int kt = (it + 1) * 128;
            const uint4* kp = (const uint4*)(kg + (size_t)(kt + tid)*DH);
            pk0 = kp[0]; pk1 = kp[1];
            const uint4* vp = (const uint4*)(vg + (size_t)(kt + tid)*DH);
            pv0 = vp[0]; pv1 = vp[1];
        }
        __syncthreads();                   // single barrier per tile

        uint32_t lh[4] = {0u, 0u, 0u, 0u};
        uint32_t kb[4];
        uint32_t scb[2][8];                 // ping-pong f16x2 scores
        ldsm_x4(kb, kaddr + boff);
        mma_h16(scb[0]+0, qa[0], kb);
        mma_h16(scb[0]+2, qa[0], kb + 2);
        mma_h16(scb[0]+4, qa[1], kb);
        mma_h16(scb[0]+6, qa[1], kb + 2);

        #pragma unroll
        for (int k4 = 0; k4 < 8; ++k4) {
            const int cur = k4 & 1, nxt = cur ^ 1;
            if (k4 < 7) {                  // QK(k4+1) overlaps exp/PV(k4)
                ldsm_x4(kb, kaddr + boff + (uint32_t)(k4+1)*768);
                mma_h16(scb[nxt]+0, qa[0], kb);
                mma_h16(scb[nxt]+2, qa[0], kb + 2);
                mma_h16(scb[nxt]+4, qa[1], kb);
                mma_h16(scb[nxt]+6, qa[1], kb + 2);
            }
            uint32_t vb[4];                // one x4t: {k0-7,k8-15} x {n0-7,n8-15}
            ldsm_x4t(vb, vaddr4 + boff + (uint32_t)k4*768);
            #pragma unroll
            for (int mt = 0; mt < 2; ++mt) {
                uint32_t pa[4];
                pa[0] = ex2h2(scb[cur][mt*4+0]);
                pa[1] = ex2h2(scb[cur][mt*4+1]);
                pa[2] = ex2h2(scb[cur][mt*4+2]);
                pa[3] = ex2h2(scb[cur][mt*4+3]);
                lh[mt*2]   = hadd2u(lh[mt*2],   hadd2u(pa[0], pa[2]));
                lh[mt*2+1] = hadd2u(lh[mt*2+1], hadd2u(pa[1], pa[3]));
                mma_fp16(of[mt][0], pa, vb,     of[mt][0]);
                mma_fp16(of[mt][1], pa, vb + 2, of[mt][1]);
            }
        }
        #pragma unroll
        for (int i = 0; i < 4; ++i) {
            float2 f = __half22float2(*reinterpret_cast<__half2*>(&lh[i]));
            lf[i] += f.x + f.y;
        }
    }

    const int b = bh >> 3, h = bh & 7;
    #pragma unroll
    for (int mt = 0; mt < 2; ++mt) {
        #pragma unroll
        for (int rr = 0; rr < 2; ++rr) {
            float l = lf[mt*2 + rr];
            l += __shfl_xor_sync(0xffffffffu, l, 1);
            l += __shfl_xor_sync(0xffffffffu, l, 2);
            float inv = 1.f / l;
            int r = wid*32 + mt*16 + rr*8 + (lane >> 2);
            __half* dst = g_aoh + ((size_t)(b*NN) + n0 + r)*NC + h*16 + (lane & 3)*2;
            *(uint32_t*)dst       = f2h2(of[mt][0][rr*2]*inv, of[mt][0][rr*2+1]*inv);
            *(uint32_t*)(dst + 8) = f2h2(of[mt][1][rr*2]*inv, of[mt][1][rr*2+1]*inv);
        }
    }
}

// ======================= Kernel C: oproj (col-split, coalesced epilogue) ====
__global__ __launch_bounds__(128) void oproj_mma_kernel(const float* __restrict__ bo)
{
    __shared__ __align__(16) __half as_[64*136];   // aoh tile; reused as os[]
    __shared__ __align__(16) __half ws[64*136];
    __shared__ float bs[64];
    __shared__ float ws1[4][4], ws2[4][4];
    float* os = (float*)as_;                       // 64*68 floats fits

    const int bi = blockIdx.x >> 7;
    const int rest = blockIdx.x & 127;
    const int chunk = rest >> 1;
    const int half = rest & 1;
    const int n0 = chunk * 64;
    const int tid = threadIdx.x, lane = tid & 31, wid = tid >> 5;
    const __half* __restrict__ wsrc = g_wh + (size_t)3*16384 + (size_t)half*64*128;

    if (tid < 64) bs[tid] = bo[half*64 + tid];

    #pragma unroll
    for (int i = tid; i < 1024; i += 128) {          // aoh tile: uint4 loads
        int row = i >> 4, u = i & 15;
        uint4 v = ((const uint4*)(g_aoh + ((size_t)(bi*NN) + n0 + row)*NC))[u];
        *(uint4*)(as_ + row*136 + u*8) = v;
    }
    #pragma unroll
    for (int i = tid; i < 1024; i += 128) {          // 64 weight rows x 128 k
        int d = i >> 4, u = i & 15;
        *(uint4*)(ws + d*136 + u*8) = ((const uint4*)wsrc)[d*16 + u];
    }
    __syncthreads();

    uint32_t qa[8][4];   // warp's 16 token rows
    {
        uint32_t base = smem_u32(as_) +
            ((uint32_t)(wid*16 + (lane & 15))*136 + ((lane >> 4) & 1)*8)*2;
        #pragma unroll
        for (int k = 0; k < 8; ++k) ldsm_x4(qa[k], base + (uint32_t)k*32);
    }

    float of[8][4];
    #pragma unroll
    for (int t = 0; t < 8; ++t)
        #pragma unroll
        for (int j = 0; j < 4; ++j) of[t][j] = 0.f;

    #pragma unroll
    for (int k = 0; k < 8; ++k) {
        uint32_t bbase = smem_u32(ws) +
            ((uint32_t)(((lane >> 4) & 1)*8 + (lane & 7))*136)*2 +
            (uint32_t)k*32 + ((lane >> 3) & 1)*16;
        #pragma unroll
        for (int g = 0; g < 4; ++g) {
            uint32_t bb[4];
            ldsm_x4(bb, bbase + (uint32_t)g*16*136*2);
            mma_fp16(of[2*g],   qa[k], bb,     of[2*g]);
            mma_fp16(of[2*g+1], qa[k], bb + 2, of[2*g+1]);
        }
    }
    __syncthreads();     // as_/ws reads done; os overlay safe

    // epilogue 1: bias + GN partials + fragment -> os[c][n] (stride 68)
    const int r = wid*16 + (lane >> 2);
    float gs1[4], gs2[4];
    #pragma unroll
    for (int g = 0; g < 4; ++g) { gs1[g] = 0.f; gs2[g] = 0.f; }

    #pragma unroll
    for (int nt = 0; nt < 8; ++nt) {
        int c0l = nt*8 + (lane & 3)*2;
        float v0 = of[nt][0] + bs[c0l];
        float v1 = of[nt][1] + bs[c0l+1];
        float v2 = of[nt][2] + bs[c0l];
        float v3 = of[nt][3] + bs[c0l+1];
        os[c0l*68 + r]         = v0;
        os[(c0l+1)*68 + r]     = v1;
        os[c0l*68 + r + 8]     = v2;
        os[(c0l+1)*68 + r + 8] = v3;
        int gl = nt >> 1;
        gs1[gl] += (v0 + v1) + (v2 + v3);
        gs2[gl] += (v0*v0 + v1*v1) + (v2*v2 + v3*v3);
    }
    #pragma unroll
    for (int g = 0; g < 4; ++g) {
        float s1 = gs1[g], s2 = gs2[g];
        #pragma unroll
        for (int o = 16; o > 0; o >>= 1) {
            s1 += __shfl_xor_sync(0xffffffffu, s1, o);
            s2 += __shfl_xor_sync(0xffffffffu, s2, o);
        }
        if (lane == 0) { ws1[wid][g] = s1; ws2[wid][g] = s2; }
    }
    __syncthreads();
    if (tid < 4) {
        float S1 = ws1[0][tid] + ws1[1][tid] + ws1[2][tid] + ws1[3][tid];
        float S2 = ws2[0][tid] + ws2[1][tid] + ws2[2][tid] + ws2[3][tid];
        g_part[(bi*NG + half*4 + tid)*64 + chunk] = make_float2(S1, S2);
    }

    // epilogue 2: coalesced stores — each channel row is 256B contiguous
    #pragma unroll
    for (int i = tid; i < 1024; i += 128) {
        int c = i >> 4, u = i & 15;
        float4 v = *(const float4*)(os + c*68 + u*4);
        *(float4*)(g_proj + (size_t)(bi*NC + half*64 + c)*NN + n0 + u*4) = v;
    }
}

// ======================= Kernel E: GN apply + residual (MLP 4) ==============
__global__ __launch_bounds__(256) void gnapply_kernel(
    const float* __restrict__ x,
    const float* __restrict__ gn_w, const float* __restrict__ gn_b,
    float* __restrict__ out)
{
    __shared__ float2 st_s;
    const int tid = threadIdx.x;
    if (tid < 32) {
        int bg = blockIdx.x >> 5;            // 32 blocks per (b,g)
        float S1 = 0.f, S2 = 0.f;
        #pragma unroll
        for (int c = tid; c < 64; c += 32) {
            float2 pp = g_part[bg*64 + c];
            S1 += pp.x; S2 += pp.y;
        }
        #pragma unroll
        for (int o = 16; o > 0; o >>= 1) {
            S1 += __shfl_xor_sync(0xffffffffu, S1, o);
            S2 += __shfl_xor_sync(0xffffffffu, S2, o);
        }
        if (tid == 0) {
            const float invn = 1.f / (16.f * NN);
            float mean = S1 * invn;
            float var  = S2 * invn - mean*mean;
            st_s = make_float2(mean, rsqrtf(var + GN_EPS));
        }
    }

    int ia = blockIdx.x * 512 + tid;
    int ib = ia + 256;
    float4 pva = ((const float4*)g_proj)[ia];
    float4 xva = ((const float4*)x)[ia];
    float4 pvb = ((const float4*)g_proj)[ib];
    float4 xvb = ((const float4*)x)[ib];
    int ca = (ia >> 10) & 127, cb = (ib >> 10) & 127;
    float gwa = gn_w[ca], gba = gn_b[ca];
    float gwb = gn_w[cb], gbb = gn_b[cb];

    __syncthreads();
    float2 st = st_s;
    float wa = gwa * st.y, wb = gwb * st.y;

    float4 oa, ob;
    oa.x = (pva.x - st.x)*wa + gba + xva.x;
    oa.y = (pva.y - st.x)*wa + gba + xva.y;
    oa.z = (pva.z - st.x)*wa + gba + xva.z;
    oa.w = (pva.w - st.x)*wa + gba + xva.w;
    ob.x = (pvb.x - st.x)*wb + gbb + xvb.x;
    ob.y = (pvb.y - st.x)*wb + gbb + xvb.y;
    ob.z = (pvb.z - st.x)*wb + gbb + xvb.z;
    ob.w = (pvb.w - st.x)*wb + gbb + xvb.w;
    ((float4*)out)[ia] = oa;
    ((float4*)out)[ib] = ob;
}

// ======================= launch =============================================
extern "C" void kernel_launch(void* const* d_in, const int* in_sizes, int n_in,
                              void* d_out, int out_size)
{
    const float* x    = (const float*)d_in[0];
    const float* Wq   = (const float*)d_in[1];
    const float* bq   = (const float*)d_in[2];
    const float* Wk   = (const float*)d_in[3];
    const float* bk   = (const float*)d_in[4];
    const float* Wv   = (const float*)d_in[5];
    const float* bv   = (const float*)d_in[6];
    const float* Wo   = (const float*)d_in[7];
    const float* bo   = (const float*)d_in[8];
    const float* gn_w = (const float*)d_in[9];
    const float* gn_b = (const float*)d_in[10];
    float* out = (float*)d_out;

    wcvt_kernel<<<128, 256>>>(Wq, Wk, Wv, Wo);
    qkv_mma_kernel<<<dim3(NB*64, 3), 128>>>(x, bq, bk, bv);
    attn_mma_kernel<<<dim3(NB*NHD, NN/128), 128>>>();
    oproj_mma_kernel<<<NB*128, 128>>>(bo);
    gnapply_kernel<<<NB*NC*NN/4/512, 256>>>(x, gn_w, gn_b, out);
}

// round 16
// speedup vs baseline: 1.1137x; 1.0259x over previous
#include <cuda_runtime.h>
#include <cuda_fp16.h>
#include <cstdint>

#define NB 2
#define NC 128
#define NN 4096      // H*W
#define NHD 8        // heads
#define DH 16        // head dim
#define NG 8         // groupnorm groups
#define GN_EPS 1e-5f
#define CSCALE 0.36067376022224085f   // 0.25 * log2(e)

// ======================= PTX helpers (baseline sm_80+ features only) =======
__device__ __forceinline__ uint32_t smem_u32(const void* p) {
    uint32_t a;
    asm("{ .reg .u64 t; cvta.to.shared.u64 t, %1; cvt.u32.u64 %0, t; }" : "=r"(a) : "l"(p));
    return a;
}
__device__ __forceinline__ void ldsm_x4(uint32_t* r, uint32_t a) {
    asm volatile("ldmatrix.sync.aligned.m8n8.x4.shared.b16 {%0,%1,%2,%3}, [%4];"
        : "=r"(r[0]), "=r"(r[1]), "=r"(r[2]), "=r"(r[3]) : "r"(a));
}
__device__ __forceinline__ void ldsm_x4t(uint32_t* r, uint32_t a) {
    asm volatile("ldmatrix.sync.aligned.m8n8.x4.trans.shared.b16 {%0,%1,%2,%3}, [%4];"
        : "=r"(r[0]), "=r"(r[1]), "=r"(r[2]), "=r"(r[3]) : "r"(a));
}
__device__ __forceinline__ void mma_fp16(float* d, const uint32_t* a,
                                         const uint32_t* b, const float* c) {
    asm volatile("mma.sync.aligned.m16n8k16.row.col.f32.f16.f16.f32 "
        "{%0,%1,%2,%3},{%4,%5,%6,%7},{%8,%9},{%10,%11,%12,%13};"
        : "=f"(d[0]), "=f"(d[1]), "=f"(d[2]), "=f"(d[3])
        : "r"(a[0]), "r"(a[1]), "r"(a[2]), "r"(a[3]), "r"(b[0]), "r"(b[1]),
          "f"(c[0]), "f"(c[1]), "f"(c[2]), "f"(c[3]));
}
// f16-accumulator HMMA: D packed f16x2 {rows r | rows r+8}
__device__ __forceinline__ void mma_h16(uint32_t* d, const uint32_t* a, const uint32_t* b) {
    uint32_t z = 0u;
    asm volatile("mma.sync.aligned.m16n8k16.row.col.f16.f16.f16.f16 "
        "{%0,%1},{%2,%3,%4,%5},{%6,%7},{%8,%9};"
        : "=r"(d[0]), "=r"(d[1])
        : "r"(a[0]), "r"(a[1]), "r"(a[2]), "r"(a[3]), "r"(b[0]), "r"(b[1]),
          "r"(z), "r"(z));
}
__device__ __forceinline__ uint32_t ex2h2(uint32_t h) {
    asm("ex2.approx.f16x2 %0, %1;" : "=r"(h) : "r"(h)); return h;
}
__device__ __forceinline__ uint32_t hadd2u(uint32_t a, uint32_t b) {
    uint32_t d; asm("add.rn.f16x2 %0, %1, %2;" : "=r"(d) : "r"(a), "r"(b)); return d;
}
__device__ __forceinline__ uint32_t f2h2(float lo, float hi) {
    __half2 h = __floats2half2_rn(lo, hi);
    return *reinterpret_cast<uint32_t*>(&h);
}

// ======================= scratch =============================================
__device__ __half g_q  [NB*NHD*NN*DH];   // [b,h,n,d], pre-scaled by CSCALE
__device__ __half g_k  [NB*NHD*NN*DH];   // [b,h,n,d]
__device__ __half g_v  [NB*NHD*NN*DH];   // [b,h,n,d]
__device__ __half g_aoh[NB*NN*NC];       // attention out fp16, [b,n,c]
__device__ float  g_proj[NB*NC*NN];      // out-proj fp32, channel-major [b,c,n]
__device__ float2 g_part[NB*NG*128];     // GN partial (sum, sumsq) per 32-token chunk
__device__ __align__(16) __half g_wh[4*NC*NC];  // fp16 weights: Wq,Wk,Wv,Wo

// ======================= Kernel W: weight fp32 -> fp16 once =================
__global__ __launch_bounds__(256) void wcvt_kernel(
    const float* __restrict__ Wq, const float* __restrict__ Wk,
    const float* __restrict__ Wv, const float* __restrict__ Wo)
{
    int i = blockIdx.x * 256 + threadIdx.x;     // float2 units, 0..32767
    int m = i >> 13, o = i & 8191;
    const float* src = (m == 0) ? Wq : (m == 1) ? Wk : (m == 2) ? Wv : Wo;
    float2 v = ((const float2*)src)[o];
    *(uint32_t*)(g_wh + (size_t)m*16384 + o*2) = f2h2(v.x, v.y);
}

// ======================= Kernel A: QKV projection (R10 shape, 128 thr) ======
__global__ __launch_bounds__(128) void qkv_mma_kernel(
    const float* __restrict__ x,
    const float* __restrict__ bq, const float* __restrict__ bk,
    const float* __restrict__ bv)
{
    __shared__ __align__(16) __half xs[64*136];
    __shared__ __align__(16) __half ws[128*72];
    __shared__ float bs[128];

    const int bi = blockIdx.x >> 6;
    const int n0 = (blockIdx.x & 63) * 64;
    const int m  = blockIdx.y;
    const int tid = threadIdx.x, lane = tid & 31, wid = tid >> 5;

    const __half* __restrict__ wsrc = g_wh + (size_t)m*16384;
    const float* __restrict__ bias  = (m == 0) ? bq : (m == 1) ? bk : bv;
    __half* __restrict__ outp       = (m == 0) ? g_q : (m == 1) ? g_k : g_v;
    const float s = (m == 0) ? CSCALE : 1.f;

    bs[tid] = bias[tid];

    {   // x tile [c=128][n=64] -> xs[n][c] fp16
        const int row = tid & 63, ch = (tid >> 6) * 64;
        const float* xp = x + (size_t)(bi*NC + ch)*NN + n0 + row;
        #pragma unroll 8
        for (int cc = 0; cc < 64; cc += 2) {
            float a = xp[(size_t)cc*NN];
            float b = xp[(size_t)(cc+1)*NN];
            *(uint32_t*)(xs + row*136 + ch + cc) = f2h2(a, b);
        }
    }
    __syncthreads();

    uint32_t qa[8][4];
    {
        uint32_t base = smem_u32(xs) +
            ((uint32_t)(wid*16 + (lane & 15))*136 + ((lane >> 4) & 1)*8)*2;
        #pragma unroll
        for (int k = 0; k < 8; ++k) ldsm_x4(qa[k], base + (uint32_t)k*32);
    }

    float of[16][4];
    #pragma unroll
    for (int t = 0; t < 16; ++t)
        #pragma unroll
        for (int j = 0; j < 4; ++j) of[t][j] = 0.f;

    for (int ph = 0; ph < 2; ++ph) {
        __syncthreads();
        #pragma unroll
        for (int i = tid; i < 1024; i += 128) {    // fp16 weight copy
            int d = i >> 3, u = i & 7;
            *(uint4*)(ws + d*72 + u*8) = *(const uint4*)(wsrc + d*128 + ph*64 + u*8);
        }
        __syncthreads();
        #pragma unroll
        for (int kk = 0; kk < 4; ++kk) {
            const int k = ph*4 + kk;
            uint32_t bbase = smem_u32(ws) +
                ((uint32_t)(((lane >> 4) & 1)*8 + (lane & 7))*72)*2 +
                (uint32_t)kk*32 + ((lane >> 3) & 1)*16;
            #pragma unroll
            for (int g = 0; g < 8; ++g) {
                uint32_t bb[4];
                ldsm_x4(bb, bbase + (uint32_t)g*16*72*2);
                mma_fp16(of[2*g],   qa[k], bb,     of[2*g]);
                mma_fp16(of[2*g+1], qa[k], bb + 2, of[2*g+1]);
            }
        }
    }

    const int r = wid*16 + (lane >> 2);
    #pragma unroll
    for (int nt = 0; nt < 16; ++nt) {
        int c0 = nt*8 + (lane & 3)*2;
        int h = c0 >> 4, d = c0 & 15;
        __half* dst = outp + ((size_t)((bi*NHD + h)*NN) + n0 + r)*DH + d;
        *(uint32_t*)dst          = f2h2((of[nt][0]+bs[c0])*s, (of[nt][1]+bs[c0+1])*s);
        *(uint32_t*)(dst + 8*DH) = f2h2((of[nt][2]+bs[c0])*s, (of[nt][3]+bs[c0+1])*s);
    }
}

// ======================= Kernel B: HMMA flash attention (double-buffered) ===
__global__ __launch_bounds__(128) void attn_mma_kernel()
{
    __shared__ __align__(16) __half qs[128*24];
    __shared__ __align__(16) __half ks[2*128*24];
    __shared__ __align__(16) __half vs[2*128*24];

    const int bh = blockIdx.x;
    const int n0 = blockIdx.y * 128;
    const int tid = threadIdx.x, lane = tid & 31, wid = tid >> 5;

    const __half* __restrict__ qg = g_q + (size_t)bh*NN*DH;
    const __half* __restrict__ kg = g_k + (size_t)bh*NN*DH;
    const __half* __restrict__ vg = g_v + (size_t)bh*NN*DH;

    {
        const uint4* q4 = (const uint4*)(qg + (size_t)(n0 + tid)*DH);
        *(uint4*)(qs + tid*24)     = q4[0];
        *(uint4*)(qs + tid*24 + 8) = q4[1];
    }
    uint4 pk0, pk1, pv0, pv1;
    {
        const uint4* kp = (const uint4*)(kg + (size_t)tid*DH);
        pk0 = kp[0]; pk1 = kp[1];
        const uint4* vp = (const uint4*)(vg + (size_t)tid*DH);
        pv0 = vp[0]; pv1 = vp[1];
    }
    __syncthreads();

    uint32_t qa[2][4];
    #pragma unroll
    for (int mt = 0; mt < 2; ++mt)
        ldsm_x4(qa[mt], smem_u32(qs) +
            ((uint32_t)(wid*32 + mt*16 + (lane & 15))*24 + ((lane >> 4) & 1)*8)*2);

    float of[2][2][4];
    #pragma unroll
    for (int a = 0; a < 2; ++a)
        #pragma unroll
        for (int b = 0; b < 2; ++b)
            #pragma unroll
            for (int c = 0; c < 4; ++c) of[a][b][c] = 0.f;
    float lf[4] = {0.f, 0.f, 0.f, 0.f};

    const uint32_t kaddr = smem_u32(ks) +
        (uint32_t)(((lane >> 4) & 1)*8 + (lane & 7))*48 + ((lane >> 3) & 1)*16;
    const uint32_t vaddr4 = smem_u32(vs) +
        (uint32_t)(lane & 15)*48 + ((lane >> 4) & 1)*16;

    #pragma unroll 2
    for (int it = 0; it < 32; ++it) {
        const uint32_t boff = (uint32_t)(it & 1) * 6144;   // bytes per buffer
        __half* ksb = ks + (it & 1)*128*24;
        __half* vsb = vs + (it & 1)*128*24;
        *(uint4*)(ksb + tid*24)     = pk0;
        *(uint4*)(ksb + tid*24 + 8) = pk1;
        *(uint4*)(vsb + tid*24)     = pv0;
        *(uint4*)(vsb + tid*24 + 8) = pv1;
        if (it + 1 < 32) {
            const int kt = (it + 1) * 128;
            const uint4* kp = (const uint4*)(kg + (size_t)(kt + tid)*DH);
            pk0 = kp[0]; pk1 = kp[1];
            const uint4* vp = (const uint4*)(vg + (size_t)(kt + tid)*DH);
            pv0 = vp[0]; pv1 = vp[1];
        }
        __syncthreads();                   // single barrier per tile

        uint32_t lh[4] = {0u, 0u, 0u, 0u};
        uint32_t kb[4];
        uint32_t scb[2][8];                 // ping-pong f16x2 scores
        ldsm_x4(kb, kaddr + boff);
        mma_h16(scb[0]+0, qa[0], kb);
        mma_h16(scb[0]+2, qa[0], kb + 2);
        mma_h16(scb[0]+4, qa[1], kb);
        mma_h16(scb[0]+6, qa[1], kb + 2);

        #pragma unroll
        for (int k4 = 0; k4 < 8; ++k4) {
            const int cur = k4 & 1, nxt = cur ^ 1;
            if (k4 < 7) {                  // QK(k4+1) overlaps exp/PV(k4)
                ldsm_x4(kb, kaddr + boff + (uint32_t)(k4+1)*768);
                mma_h16(scb[nxt]+0, qa[0], kb);
                mma_h16(scb[nxt]+2, qa[0], kb + 2);
                mma_h16(scb[nxt]+4, qa[1], kb);
                mma_h16(scb[nxt]+6, qa[1], kb + 2);
            }
            uint32_t vb[4];                // one x4t: {k0-7,k8-15} x {n0-7,n8-15}
            ldsm_x4t(vb, vaddr4 + boff + (uint32_t)k4*768);
            #pragma unroll
            for (int mt = 0; mt < 2; ++mt) {
                uint32_t pa[4];
                pa[0] = ex2h2(scb[cur][mt*4+0]);
                pa[1] = ex2h2(scb[cur][mt*4+1]);
                pa[2] = ex2h2(scb[cur][mt*4+2]);
                pa[3] = ex2h2(scb[cur][mt*4+3]);
                lh[mt*2]   = hadd2u(lh[mt*2],   hadd2u(pa[0], pa[2]));
                lh[mt*2+1] = hadd2u(lh[mt*2+1], hadd2u(pa[1], pa[3]));
                mma_fp16(of[mt][0], pa, vb,     of[mt][0]);
                mma_fp16(of[mt][1], pa, vb + 2, of[mt][1]);
            }
        }
        #pragma unroll
        for (int i = 0; i < 4; ++i) {
            float2 f = __half22float2(*reinterpret_cast<__half2*>(&lh[i]));
            lf[i] += f.x + f.y;
        }
    }

    const int b = bh >> 3, h = bh & 7;
    #pragma unroll
    for (int mt = 0; mt < 2; ++mt) {
        #pragma unroll
        for (int rr = 0; rr < 2; ++rr) {
            float l = lf[mt*2 + rr];
            l += __shfl_xor_sync(0xffffffffu, l, 1);
            l += __shfl_xor_sync(0xffffffffu, l, 2);
            float inv = 1.f / l;
            int r = wid*32 + mt*16 + rr*8 + (lane >> 2);
            __half* dst = g_aoh + ((size_t)(b*NN) + n0 + r)*NC + h*16 + (lane & 3)*2;
            *(uint32_t*)dst       = f2h2(of[mt][0][rr*2]*inv, of[mt][0][rr*2+1]*inv);
            *(uint32_t*)(dst + 8) = f2h2(of[mt][1][rr*2]*inv, of[mt][1][rr*2+1]*inv);
        }
    }
}

// ======================= Kernel C: oproj (32-token x 64-col CTAs) ===========
// grid NB*256: CTA = (bi, 32-token chunk, 64-outcol half). 4 warps =
// 2 m-tiles x 2 col-quarters. Single-shot staging, coalesced epilogue.
__global__ __launch_bounds__(128) void oproj_mma_kernel(const float* __restrict__ bo)
{
    __shared__ __align__(16) __half as_[32*136];   // 8.7KB aoh tile
    __shared__ __align__(16) __half ws[64*136];    // 17.4KB weights; os overlay
    __shared__ float bs[64];
    __shared__ float ws1[4][2], ws2[4][2];
    float* os = (float*)ws;                        // 64*36 floats = 9.2KB fits

    const int bi = blockIdx.x >> 8;
    const int rest = blockIdx.x & 255;
    const int chunk = rest >> 1;                   // 0..127 (32-token chunks)
    const int half = rest & 1;
    const int n0 = chunk * 32;
    const int tid = threadIdx.x, lane = tid & 31, wid = tid >> 5;
    const int mt = wid & 1, cq = wid >> 1;         // m-tile, 32-col quarter
    const __half* __restrict__ wsrc = g_wh + (size_t)3*16384 + (size_t)half*64*128;

    if (tid < 64) bs[tid] = bo[half*64 + tid];

    #pragma unroll
    for (int i = tid; i < 512; i += 128) {         // aoh 32 rows x 16 uint4
        int row = i >> 4, u = i & 15;
        uint4 v = ((const uint4*)(g_aoh + ((size_t)(bi*NN) + n0 + row)*NC))[u];
        *(uint4*)(as_ + row*136 + u*8) = v;
    }
    #pragma unroll
    for (int i = tid; i < 1024; i += 128) {        // 64 weight rows x 16 uint4
        int d = i >> 4, u = i & 15;
        *(uint4*)(ws + d*136 + u*8) = ((const uint4*)wsrc)[d*16 + u];
    }
    __syncthreads();

    uint32_t qa[8][4];   // warp's 16 token rows
    {
        uint32_t base = smem_u32(as_) +
            ((uint32_t)(mt*16 + (lane & 15))*136 + ((lane >> 4) & 1)*8)*2;
        #pragma unroll
        for (int k = 0; k < 8; ++k) ldsm_x4(qa[k], base + (uint32_t)k*32);
    }

    float of[4][4];
    #pragma unroll
    for (int t = 0; t < 4; ++t)
        #pragma unroll
        for (int j = 0; j < 4; ++j) of[t][j] = 0.f;

    #pragma unroll
    for (int k = 0; k < 8; ++k) {
        uint32_t bbase = smem_u32(ws) +
            ((uint32_t)(cq*32 + ((lane >> 4) & 1)*8 + (lane & 7))*136)*2 +
            (uint32_t)k*32 + ((lane >> 3) & 1)*16;
        #pragma unroll
        for (int g = 0; g < 2; ++g) {
            uint32_t bb[4];
            ldsm_x4(bb, bbase + (uint32_t)g*16*136*2);
            mma_fp16(of[2*g],   qa[k], bb,     of[2*g]);
            mma_fp16(of[2*g+1], qa[k], bb + 2, of[2*g+1]);
        }
    }
    __syncthreads();     // ws reads done; os overlay safe

    // epilogue 1: bias + GN partials + fragment -> os[c][n] (stride 36)
    const int r = mt*16 + (lane >> 2);
    float gs1[2] = {0.f, 0.f}, gs2[2] = {0.f, 0.f};

    #pragma unroll
    for (int nt = 0; nt < 4; ++nt) {
        int c0l = cq*32 + nt*8 + (lane & 3)*2;     // local col in 64-half
        float v0 = of[nt][0] + bs[c0l];
        float v1 = of[nt][1] + bs[c0l+1];
        float v2 = of[nt][2] + bs[c0l];
        float v3 = of[nt][3] + bs[c0l+1];
        os[c0l*36 + r]         = v0;
        os[(c0l+1)*36 + r]     = v1;
        os[c0l*36 + r + 8]     = v2;
        os[(c0l+1)*36 + r + 8] = v3;
        int gl = nt >> 1;                          // 2 local groups per quarter
        gs1[gl] += (v0 + v1) + (v2 + v3);
        gs2[gl] += (v0*v0 + v1*v1) + (v2*v2 + v3*v3);
    }
    #pragma unroll
    for (int g = 0; g < 2; ++g) {
        float s1 = gs1[g], s2 = gs2[g];
        #pragma unroll
        for (int o = 16; o > 0; o >>= 1) {
            s1 += __shfl_xor_sync(0xffffffffu, s1, o);
            s2 += __shfl_xor_sync(0xffffffffu, s2, o);
        }
        if (lane == 0) { ws1[wid][g] = s1; ws2[wid][g] = s2; }
    }
    __syncthreads();
    if (tid < 4) {       // local group tid = cq_*2 + gl; warps cq_*2 + {0,1}
        int cq_ = tid >> 1, gl = tid & 1;
        float S1 = ws1[cq_*2][gl] + ws1[cq_*2+1][gl];
        float S2 = ws2[cq_*2][gl] + ws2[cq_*2+1][gl];
        g_part[(bi*NG + half*4 + tid)*128 + chunk] = make_float2(S1, S2);
    }

    // epilogue 2: coalesced stores — each channel row is 128B contiguous
    #pragma unroll
    for (int i = tid; i < 512; i += 128) {
        int c = i >> 3, u = i & 7;
        float4 v = *(const float4*)(os + c*36 + u*4);
        *(float4*)(g_proj + (size_t)(bi*NC + half*64 + c)*NN + n0 + u*4) = v;
    }
}

// ======================= Kernel E: GN apply + residual (MLP 4) ==============
__global__ __launch_bounds__(256) void gnapply_kernel(
    const float* __restrict__ x,
    const float* __restrict__ gn_w, const float* __restrict__ gn_b,
    float* __restrict__ out)
{
    __shared__ float2 st_s;
    const int tid = threadIdx.x;
    if (tid < 32) {
        int bg = blockIdx.x >> 5;            // 32 blocks per (b,g)
        float S1 = 0.f, S2 = 0.f;
        #pragma unroll
        for (int c = tid; c < 128; c += 32) {
            float2 pp = g_part[bg*128 + c];
            S1 += pp.x; S2 += pp.y;
        }
        #pragma unroll
        for (int o = 16; o > 0; o >>= 1) {
            S1 += __shfl_xor_sync(0xffffffffu, S1, o);
            S2 += __shfl_xor_sync(0xffffffffu, S2, o);
        }
        if (tid == 0) {
            const float invn = 1.f / (16.f * NN);
            float mean = S1 * invn;
            float var  = S2 * invn - mean*mean;
            st_s = make_float2(mean, rsqrtf(var + GN_EPS));
        }
    }

    int ia = blockIdx.x * 512 + tid;
    int ib = ia + 256;
    float4 pva = ((const float4*)g_proj)[ia];
    float4 xva = ((const float4*)x)[ia];
    float4 pvb = ((const float4*)g_proj)[ib];
    float4 xvb = ((const float4*)x)[ib];
    int ca = (ia >> 10) & 127, cb = (ib >> 10) & 127;
    float gwa = gn_w[ca], gba = gn_b[ca];
    float gwb = gn_w[cb], gbb = gn_b[cb];

    __syncthreads();
    float2 st = st_s;
    float wa = gwa * st.y, wb = gwb * st.y;

    float4 oa, ob;
    oa.x = (pva.x - st.x)*wa + gba + xva.x;
    oa.y = (pva.y - st.x)*wa + gba + xva.y;
    oa.z = (pva.z - st.x)*wa + gba + xva.z;
    oa.w = (pva.w - st.x)*wa + gba + xva.w;
    ob.x = (pvb.x - st.x)*wb + gbb + xvb.x;
    ob.y = (pvb.y - st.x)*wb + gbb + xvb.y;
    ob.z = (pvb.z - st.x)*wb + gbb + xvb.z;
    ob.w = (pvb.w - st.x)*wb + gbb + xvb.w;
    ((float4*)out)[ia] = oa;
    ((float4*)out)[ib] = ob;
}

// ======================= launch =============================================
extern "C" void kernel_launch(void* const* d_in, const int* in_sizes, int n_in,
                              void* d_out, int out_size)
{
    const float* x    = (const float*)d_in[0];
    const float* Wq   = (const float*)d_in[1];
    const float* bq   = (const float*)d_in[2];
    const float* Wk   = (const float*)d_in[3];
    const float* bk   = (const float*)d_in[4];
    const float* Wv   = (const float*)d_in[5];
    const float* bv   = (const float*)d_in[6];
    const float* Wo   = (const float*)d_in[7];
    const float* bo   = (const float*)d_in[8];
    const float* gn_w = (const float*)d_in[9];
    const float* gn_b = (const float*)d_in[10];
    float* out = (float*)d_out;

    wcvt_kernel<<<128, 256>>>(Wq, Wk, Wv, Wo);
    qkv_mma_kernel<<<dim3(NB*64, 3), 128>>>(x, bq, bk, bv);
    attn_mma_kernel<<<dim3(NB*NHD, NN/128), 128>>>();
    oproj_mma_kernel<<<NB*256, 128>>>(bo);
    gnapply_kernel<<<NB*NC*NN/4/512, 256>>>(x, gn_w, gn_b, out);
}

// round 17
// speedup vs baseline: 1.1173x; 1.0032x over previous
#include <cuda_runtime.h>
#include <cuda_fp16.h>
#include <cstdint>

#define NB 2
#define NC 128
#define NN 4096      // H*W
#define NHD 8        // heads
#define DH 16        // head dim
#define NG 8         // groupnorm groups
#define GN_EPS 1e-5f
#define CSCALE 0.36067376022224085f   // 0.25 * log2(e)

// ======================= PTX helpers (baseline sm_80+ features only) =======
__device__ __forceinline__ uint32_t smem_u32(const void* p) {
    uint32_t a;
    asm("{ .reg .u64 t; cvta.to.shared.u64 t, %1; cvt.u32.u64 %0, t; }" : "=r"(a) : "l"(p));
    return a;
}
__device__ __forceinline__ void ldsm_x4(uint32_t* r, uint32_t a) {
    asm volatile("ldmatrix.sync.aligned.m8n8.x4.shared.b16 {%0,%1,%2,%3}, [%4];"
        : "=r"(r[0]), "=r"(r[1]), "=r"(r[2]), "=r"(r[3]) : "r"(a));
}
__device__ __forceinline__ void ldsm_x4t(uint32_t* r, uint32_t a) {
    asm volatile("ldmatrix.sync.aligned.m8n8.x4.trans.shared.b16 {%0,%1,%2,%3}, [%4];"
        : "=r"(r[0]), "=r"(r[1]), "=r"(r[2]), "=r"(r[3]) : "r"(a));
}
__device__ __forceinline__ void mma_fp16(float* d, const uint32_t* a,
                                         const uint32_t* b, const float* c) {
    asm volatile("mma.sync.aligned.m16n8k16.row.col.f32.f16.f16.f32 "
        "{%0,%1,%2,%3},{%4,%5,%6,%7},{%8,%9},{%10,%11,%12,%13};"
        : "=f"(d[0]), "=f"(d[1]), "=f"(d[2]), "=f"(d[3])
        : "r"(a[0]), "r"(a[1]), "r"(a[2]), "r"(a[3]), "r"(b[0]), "r"(b[1]),
          "f"(c[0]), "f"(c[1]), "f"(c[2]), "f"(c[3]));
}
// f16-accumulator HMMA: D packed f16x2 {rows r | rows r+8}
__device__ __forceinline__ void mma_h16(uint32_t* d, const uint32_t* a, const uint32_t* b) {
    uint32_t z = 0u;
    asm volatile("mma.sync.aligned.m16n8k16.row.col.f16.f16.f16.f16 "
        "{%0,%1},{%2,%3,%4,%5},{%6,%7},{%8,%9};"
        : "=r"(d[0]), "=r"(d[1])
        : "r"(a[0]), "r"(a[1]), "r"(a[2]), "r"(a[3]), "r"(b[0]), "r"(b[1]),
          "r"(z), "r"(z));
}
__device__ __forceinline__ uint32_t ex2h2(uint32_t h) {
    asm("ex2.approx.f16x2 %0, %1;" : "=r"(h) : "r"(h)); return h;
}
__device__ __forceinline__ uint32_t hadd2u(uint32_t a, uint32_t b) {
    uint32_t d; asm("add.rn.f16x2 %0, %1, %2;" : "=r"(d) : "r"(a), "r"(b)); return d;
}
__device__ __forceinline__ uint32_t f2h2(float lo, float hi) {
    __half2 h = __floats2half2_rn(lo, hi);
    return *reinterpret_cast<uint32_t*>(&h);
}

// ======================= scratch =============================================
__device__ __half g_q  [NB*NHD*NN*DH];   // [b,h,n,d], pre-scaled by CSCALE
__device__ __half g_k  [NB*NHD*NN*DH];   // [b,h,n,d]
__device__ __half g_v  [NB*NHD*NN*DH];   // [b,h,n,d]
__device__ __half g_aoh[NB*NN*NC];       // attention out fp16, [b,n,c]
__device__ float  g_proj[NB*NC*NN];      // out-proj fp32, channel-major [b,c,n]
__device__ float2 g_part[NB*NG*128];     // GN partial (sum, sumsq) per 32-token chunk
__device__ __align__(16) __half g_wh[4*NC*NC];  // fp16 weights: Wq,Wk,Wv,Wo
__device__ __align__(16) __half g_xh[NB*NN*NC]; // fp16 x, transposed [b,n,c]

// ======================= Kernel W: weights + x -> fp16 once ==================
// blocks 0..127: weight convert; blocks 128..255: x transpose+convert.
__global__ __launch_bounds__(256) void cvt_kernel(
    const float* __restrict__ x,
    const float* __restrict__ Wq, const float* __restrict__ Wk,
    const float* __restrict__ Wv, const float* __restrict__ Wo)
{
    __shared__ __align__(16) __half xs[64*136];
    const int tid = threadIdx.x;
    if (blockIdx.x < 128) {
        int i = blockIdx.x * 256 + tid;     // float2 units, 0..32767
        int m = i >> 13, o = i & 8191;
        const float* src = (m == 0) ? Wq : (m == 1) ? Wk : (m == 2) ? Wv : Wo;
        float2 v = ((const float2*)src)[o];
        *(uint32_t*)(g_wh + (size_t)m*16384 + o*2) = f2h2(v.x, v.y);
        return;
    }
    const int t = blockIdx.x - 128;          // 0..127
    const int bi = t >> 6, n0 = (t & 63) * 64;
    {   // x tile [c=128][n=64] -> xs[n][c] fp16 (256 threads: 32 cols each)
        const int row = tid & 63, ch = (tid >> 6) * 32;
        const float* xp = x + (size_t)(bi*NC + ch)*NN + n0 + row;
        #pragma unroll 4
        for (int cc = 0; cc < 32; cc += 2) {
            float a = xp[(size_t)cc*NN];
            float b = xp[(size_t)(cc+1)*NN];
            *(uint32_t*)(xs + row*136 + ch + cc) = f2h2(a, b);
        }
    }
    __syncthreads();
    #pragma unroll
    for (int i = tid; i < 1024; i += 256) {  // coalesced 256B rows out
        int row = i >> 4, u = i & 15;
        ((uint4*)(g_xh + ((size_t)(bi*NN) + n0 + row)*NC))[u] =
            *(const uint4*)(xs + row*136 + u*8);
    }
}

// ======================= Kernel A: QKV projection (fp16 x, uint4 prologue) ==
__global__ __launch_bounds__(128) void qkv_mma_kernel(
    const float* __restrict__ bq, const float* __restrict__ bk,
    const float* __restrict__ bv)
{
    __shared__ __align__(16) __half xs[64*136];
    __shared__ __align__(16) __half ws[128*72];
    __shared__ float bs[128];

    const int bi = blockIdx.x >> 6;
    const int n0 = (blockIdx.x & 63) * 64;
    const int m  = blockIdx.y;
    const int tid = threadIdx.x, lane = tid & 31, wid = tid >> 5;

    const __half* __restrict__ wsrc = g_wh + (size_t)m*16384;
    const float* __restrict__ bias  = (m == 0) ? bq : (m == 1) ? bk : bv;
    __half* __restrict__ outp       = (m == 0) ? g_q : (m == 1) ? g_k : g_v;
    const float s = (m == 0) ? CSCALE : 1.f;

    bs[tid] = bias[tid];

    #pragma unroll
    for (int i = tid; i < 1024; i += 128) {  // x tile: uint4 copies (fp16)
        int row = i >> 4, u = i & 15;
        uint4 v = ((const uint4*)(g_xh + ((size_t)(bi*NN) + n0 + row)*NC))[u];
        *(uint4*)(xs + row*136 + u*8) = v;
    }
    __syncthreads();

    uint32_t qa[8][4];
    {
        uint32_t base = smem_u32(xs) +
            ((uint32_t)(wid*16 + (lane & 15))*136 + ((lane >> 4) & 1)*8)*2;
        #pragma unroll
        for (int k = 0; k < 8; ++k) ldsm_x4(qa[k], base + (uint32_t)k*32);
    }

    float of[16][4];
    #pragma unroll
    for (int t = 0; t < 16; ++t)
        #pragma unroll
        for (int j = 0; j < 4; ++j) of[t][j] = 0.f;

    for (int ph = 0; ph < 2; ++ph) {
        __syncthreads();
        #pragma unroll
        for (int i = tid; i < 1024; i += 128) {    // fp16 weight copy
            int d = i >> 3, u = i & 7;
            *(uint4*)(ws + d*72 + u*8) = *(const uint4*)(wsrc + d*128 + ph*64 + u*8);
        }
        __syncthreads();
        #pragma unroll
        for (int kk = 0; kk < 4; ++kk) {
            const int k = ph*4 + kk;
            uint32_t bbase = smem_u32(ws) +
                ((uint32_t)(((lane >> 4) & 1)*8 + (lane & 7))*72)*2 +
                (uint32_t)kk*32 + ((lane >> 3) & 1)*16;
            #pragma unroll
            for (int g = 0; g < 8; ++g) {
                uint32_t bb[4];
                ldsm_x4(bb, bbase + (uint32_t)g*16*72*2);
                mma_fp16(of[2*g],   qa[k], bb,     of[2*g]);
                mma_fp16(of[2*g+1], qa[k], bb + 2, of[2*g+1]);
            }
        }
    }

    const int r = wid*16 + (lane >> 2);
    #pragma unroll
    for (int nt = 0; nt < 16; ++nt) {
        int c0 = nt*8 + (lane & 3)*2;
        int h = c0 >> 4, d = c0 & 15;
        __half* dst = outp + ((size_t)((bi*NHD + h)*NN) + n0 + r)*DH + d;
        *(uint32_t*)dst          = f2h2((of[nt][0]+bs[c0])*s, (of[nt][1]+bs[c0+1])*s);
        *(uint32_t*)(dst + 8*DH) = f2h2((of[nt][2]+bs[c0])*s, (of[nt][3]+bs[c0+1])*s);
    }
}

// ======================= Kernel B: HMMA flash attention (double-buffered) ===
__global__ __launch_bounds__(128) void attn_mma_kernel()
{
    __shared__ __align__(16) __half qs[128*24];
    __shared__ __align__(16) __half ks[2*128*24];
    __shared__ __align__(16) __half vs[2*128*24];

    const int bh = blockIdx.x;
    const int n0 = blockIdx.y * 128;
    const int tid = threadIdx.x, lane = tid & 31, wid = tid >> 5;

    const __half* __restrict__ qg = g_q + (size_t)bh*NN*DH;
    const __half* __restrict__ kg = g_k + (size_t)bh*NN*DH;
    const __half* __restrict__ vg = g_v + (size_t)bh*NN*DH;

    {
        const uint4* q4 = (const uint4*)(qg + (size_t)(n0 + tid)*DH);
        *(uint4*)(qs + tid*24)     = q4[0];
        *(uint4*)(qs + tid*24 + 8) = q4[1];
    }
    uint4 pk0, pk1, pv0, pv1;
    {
        const uint4* kp = (const uint4*)(kg + (size_t)tid*DH);
        pk0 = kp[0]; pk1 = kp[1];
        const uint4* vp = (const uint4*)(vg + (size_t)tid*DH);
        pv0 = vp[0]; pv1 = vp[1];
    }
    __syncthreads();

    uint32_t qa[2][4];
    #pragma unroll
    for (int mt = 0; mt < 2; ++mt)
        ldsm_x4(qa[mt], smem_u32(qs) +
            ((uint32_t)(wid*32 + mt*16 + (lane & 15))*24 + ((lane >> 4) & 1)*8)*2);

    float of[2][2][4];
    #pragma unroll
    for (int a = 0; a < 2; ++a)
        #pragma unroll
        for (int b = 0; b < 2; ++b)
            #pragma unroll
            for (int c = 0; c < 4; ++c) of[a][b][c] = 0.f;
    float lf[4] = {0.f, 0.f, 0.f, 0.f};

    const uint32_t kaddr = smem_u32(ks) +
        (uint32_t)(((lane >> 4) & 1)*8 + (lane & 7))*48 + ((lane >> 3) & 1)*16;
    const uint32_t vaddr4 = smem_u32(vs) +
        (uint32_t)(lane & 15)*48 + ((lane >> 4) & 1)*16;

    #pragma unroll 2
    for (int it = 0; it < 32; ++it) {
        const uint32_t boff = (uint32_t)(it & 1) * 6144;   // bytes per buffer
        __half* ksb = ks + (it & 1)*128*24;
        __half* vsb = vs + (it & 1)*128*24;
        *(uint4*)(ksb + tid*24)     = pk0;
        *(uint4*)(ksb + tid*24 + 8) = pk1;
        *(uint4*)(vsb + tid*24)     = pv0;
        *(uint4*)(vsb + tid*24 + 8) = pv1;
        if (it + 1 < 32) {
            const int kt = (it + 1) * 128;
            const uint4* kp = (const uint4*)(kg + (size_t)(kt + tid)*DH);
            pk0 = kp[0]; pk1 = kp[1];
            const uint4* vp = (const uint4*)(vg + (size_t)(kt + tid)*DH);
            pv0 = vp[0]; pv1 = vp[1];
        }
        __syncthreads();                   // single barrier per tile

        uint32_t lh[4] = {0u, 0u, 0u, 0u};
        uint32_t kb[4];
        uint32_t scb[2][8];                 // ping-pong f16x2 scores
        ldsm_x4(kb, kaddr + boff);
        mma_h16(scb[0]+0, qa[0], kb);
        mma_h16(scb[0]+2, qa[0], kb + 2);
        mma_h16(scb[0]+4, qa[1], kb);
        mma_h16(scb[0]+6, qa[1], kb + 2);

        #pragma unroll
        for (int k4 = 0; k4 < 8; ++k4) {
            const int cur = k4 & 1, nxt = cur ^ 1;
            if (k4 < 7) {                  // QK(k4+1) overlaps exp/PV(k4)
                ldsm_x4(kb, kaddr + boff + (uint32_t)(k4+1)*768);
                mma_h16(scb[nxt]+0, qa[0], kb);
                mma_h16(scb[nxt]+2, qa[0], kb + 2);
                mma_h16(scb[nxt]+4, qa[1], kb);
                mma_h16(scb[nxt]+6, qa[1], kb + 2);
            }
            uint32_t vb[4];                // one x4t: {k0-7,k8-15} x {n0-7,n8-15}
            ldsm_x4t(vb, vaddr4 + boff + (uint32_t)k4*768);
            #pragma unroll
            for (int mt = 0; mt < 2; ++mt) {
                uint32_t pa[4];
                pa[0] = ex2h2(scb[cur][mt*4+0]);
                pa[1] = ex2h2(scb[cur][mt*4+1]);
                pa[2] = ex2h2(scb[cur][mt*4+2]);
                pa[3] = ex2h2(scb[cur][mt*4+3]);
                lh[mt*2]   = hadd2u(lh[mt*2],   hadd2u(pa[0], pa[2]));
                lh[mt*2+1] = hadd2u(lh[mt*2+1], hadd2u(pa[1], pa[3]));
                mma_fp16(of[mt][0], pa, vb,     of[mt][0]);
                mma_fp16(of[mt][1], pa, vb + 2, of[mt][1]);
            }
        }
        #pragma unroll
        for (int i = 0; i < 4; ++i) {
            float2 f = __half22float2(*reinterpret_cast<__half2*>(&lh[i]));
            lf[i] += f.x + f.y;
        }
    }

    const int b = bh >> 3, h = bh & 7;
    #pragma unroll
    for (int mt = 0; mt < 2; ++mt) {
        #pragma unroll
        for (int rr = 0; rr < 2; ++rr) {
            float l = lf[mt*2 + rr];
            l += __shfl_xor_sync(0xffffffffu, l, 1);
            l += __shfl_xor_sync(0xffffffffu, l, 2);
            float inv = 1.f / l;
            int r = wid*32 + mt*16 + rr*8 + (lane >> 2);
            __half* dst = g_aoh + ((size_t)(b*NN) + n0 + r)*NC + h*16 + (lane & 3)*2;
            *(uint32_t*)dst       = f2h2(of[mt][0][rr*2]*inv, of[mt][0][rr*2+1]*inv);
            *(uint32_t*)(dst + 8) = f2h2(of[mt][1][rr*2]*inv, of[mt][1][rr*2+1]*inv);
        }
    }
}

// ======================= Kernel C: oproj (32-token x 64-col CTAs) ===========
__global__ __launch_bounds__(128) void oproj_mma_kernel(const float* __restrict__ bo)
{
    __shared__ __align__(16) __half as_[32*136];   // 8.7KB aoh tile
    __shared__ __align__(16) __half ws[64*136];    // 17.4KB weights; os overlay
    __shared__ float bs[64];
    __shared__ float ws1[4][2], ws2[4][2];
    float* os = (float*)ws;                        // 64*36 floats fits

    const int bi = blockIdx.x >> 8;
    const int rest = blockIdx.x & 255;
    const int chunk = rest >> 1;                   // 0..127 (32-token chunks)
    const int half = rest & 1;
    const int n0 = chunk * 32;
    const int tid = threadIdx.x, lane = tid & 31, wid = tid >> 5;
    const int mt = wid & 1, cq = wid >> 1;         // m-tile, 32-col quarter
    const __half* __restrict__ wsrc = g_wh + (size_t)3*16384 + (size_t)half*64*128;

    if (tid < 64) bs[tid] = bo[half*64 + tid];

    #pragma unroll
    for (int i = tid; i < 512; i += 128) {         // aoh 32 rows x 16 uint4
        int row = i >> 4, u = i & 15;
        uint4 v = ((const uint4*)(g_aoh + ((size_t)(bi*NN) + n0 + row)*NC))[u];
        *(uint4*)(as_ + row*136 + u*8) = v;
    }
    #pragma unroll
    for (int i = tid; i < 1024; i += 128) {        // 64 weight rows x 16 uint4
        int d = i >> 4, u = i & 15;
        *(uint4*)(ws + d*136 + u*8) = ((const uint4*)wsrc)[d*16 + u];
    }
    __syncthreads();

    uint32_t qa[8][4];   // warp's 16 token rows
    {
        uint32_t base = smem_u32(as_) +
            ((uint32_t)(mt*16 + (lane & 15))*136 + ((lane >> 4) & 1)*8)*2;
        #pragma unroll
        for (int k = 0; k < 8; ++k) ldsm_x4(qa[k], base + (uint32_t)k*32);
    }

    float of[4][4];
    #pragma unroll
    for (int t = 0; t < 4; ++t)
        #pragma unroll
        for (int j = 0; j < 4; ++j) of[t][j] = 0.f;

    #pragma unroll
    for (int k = 0; k < 8; ++k) {
        uint32_t bbase = smem_u32(ws) +
            ((uint32_t)(cq*32 + ((lane >> 4) & 1)*8 + (lane & 7))*136)*2 +
            (uint32_t)k*32 + ((lane >> 3) & 1)*16;
        #pragma unroll
        for (int g = 0; g < 2; ++g) {
            uint32_t bb[4];
            ldsm_x4(bb, bbase + (uint32_t)g*16*136*2);
            mma_fp16(of[2*g],   qa[k], bb,     of[2*g]);
            mma_fp16(of[2*g+1], qa[k], bb + 2, of[2*g+1]);
        }
    }
    __syncthreads();     // ws reads done; os overlay safe

    // epilogue 1: bias + GN partials + fragment -> os[c][n] (stride 36)
    const int r = mt*16 + (lane >> 2);
    float gs1[2] = {0.f, 0.f}, gs2[2] = {0.f, 0.f};

    #pragma unroll
    for (int nt = 0; nt < 4; ++nt) {
        int c0l = cq*32 + nt*8 + (lane & 3)*2;     // local col in 64-half
        float v0 = of[nt][0] + bs[c0l];
        float v1 = of[nt][1] + bs[c0l+1];
        float v2 = of[nt][2] + bs[c0l];
        float v3 = of[nt][3] + bs[c0l+1];
        os[c0l*36 + r]         = v0;
        os[(c0l+1)*36 + r]     = v1;
        os[c0l*36 + r + 8]     = v2;
        os[(c0l+1)*36 + r + 8] = v3;
        int gl = nt >> 1;
        gs1[gl] += (v0 + v1) + (v2 + v3);
        gs2[gl] += (v0*v0 + v1*v1) + (v2*v2 + v3*v3);
    }
    #pragma unroll
    for (int g = 0; g < 2; ++g) {
        float s1 = gs1[g], s2 = gs2[g];
        #pragma unroll
        for (int o = 16; o > 0; o >>= 1) {
            s1 += __shfl_xor_sync(0xffffffffu, s1, o);
            s2 += __shfl_xor_sync(0xffffffffu, s2, o);
        }
        if (lane == 0) { ws1[wid][g] = s1; ws2[wid][g] = s2; }
    }
    __syncthreads();
    if (tid < 4) {
        int cq_ = tid >> 1, gl = tid & 1;
        float S1 = ws1[cq_*2][gl] + ws1[cq_*2+1][gl];
        float S2 = ws2[cq_*2][gl] + ws2[cq_*2+1][gl];
        g_part[(bi*NG + half*4 + tid)*128 + chunk] = make_float2(S1, S2);
    }

    // epilogue 2: coalesced stores — each channel row is 128B contiguous
    #pragma unroll
    for (int i = tid; i < 512; i += 128) {
        int c = i >> 3, u = i & 7;
        float4 v = *(const float4*)(os + c*36 + u*4);
        *(float4*)(g_proj + (size_t)(bi*NC + half*64 + c)*NN + n0 + u*4) = v;
    }
}

// ======================= Kernel E: GN apply (one channel per block) =========
// grid 256: block = (bi, c); 4 float4 per thread, channel constants hoisted.
__global__ __launch_bounds__(256) void gnapply_kernel(
    const float* __restrict__ x,
    const float* __restrict__ gn_w, const float* __restrict__ gn_b,
    float* __restrict__ out)
{
    __shared__ float2 st_s;
    const int tid = threadIdx.x;
    const int bi = blockIdx.x >> 7, c = blockIdx.x & 127;
    const int bg = bi*NG + (c >> 4);
    const float gw = gn_w[c], gb = gn_b[c];

    if (tid < 32) {
        float S1 = 0.f, S2 = 0.f;
        #pragma unroll
        for (int k = tid; k < 128; k += 32) {
            float2 pp = g_part[bg*128 + k];
            S1 += pp.x; S2 += pp.y;
        }
        #pragma unroll
        for (int o = 16; o > 0; o >>= 1) {
            S1 += __shfl_xor_sync(0xffffffffu, S1, o);
            S2 += __shfl_xor_sync(0xffffffffu, S2, o);
        }
        if (tid == 0) {
            const float invn = 1.f / (16.f * NN);
            float mean = S1 * invn;
            float var  = S2 * invn - mean*mean;
            st_s = make_float2(mean, rsqrtf(var + GN_EPS));
        }
    }

    const int base = blockIdx.x * 1024;      // float4 units; block = 1 channel
    float4 pv[4], xv[4];
    #pragma unroll
    for (int j = 0; j < 4; ++j) {
        pv[j] = ((const float4*)g_proj)[base + tid + j*256];
        xv[j] = ((const float4*)x)[base + tid + j*256];
    }
    __syncthreads();
    float2 st = st_s;
    float w = gw * st.y;

    #pragma unroll
    for (int j = 0; j < 4; ++j) {
        float4 o;
        o.x = (pv[j].x - st.x)*w + gb + xv[j].x;
        o.y = (pv[j].y - st.x)*w + gb + xv[j].y;
        o.z = (pv[j].z - st.x)*w + gb + xv[j].z;
        o.w = (pv[j].w - st.x)*w + gb + xv[j].w;
        ((float4*)out)[base + tid + j*256] = o;
    }
}

// ======================= launch =============================================
extern "C" void kernel_launch(void* const* d_in, const int* in_sizes, int n_in,
                              void* d_out, int out_size)
{
    const float* x    = (const float*)d_in[0];
    const float* Wq   = (const float*)d_in[1];
    const float* bq   = (const float*)d_in[2];
    const float* Wk   = (const float*)d_in[3];
    const float* bk   = (const float*)d_in[4];
    const float* Wv   = (const float*)d_in[5];
    const float* bv   = (const float*)d_in[6];
    const float* Wo   = (const float*)d_in[7];
    const float* bo   = (const float*)d_in[8];
    const float* gn_w = (const float*)d_in[9];
    const float* gn_b = (const float*)d_in[10];
    float* out = (float*)d_out;

    cvt_kernel<<<256, 256>>>(x, Wq, Wk, Wv, Wo);
    qkv_mma_kernel<<<dim3(NB*64, 3), 128>>>(bq, bk, bv);
    attn_mma_kernel<<<dim3(NB*NHD, NN/128), 128>>>();
    oproj_mma_kernel<<<NB*256, 128>>>(bo);
    gnapply_kernel<<<NB*NC, 256>>>(x, gn_w, gn_b, out);
}